// round 7
// baseline (speedup 1.0000x reference)
#include <cuda_runtime.h>
#include <cuda_bf16.h>
#include <math.h>

#define VOCAB 32000
#define EMB   256
#define UNITS 512
#define NB    32
#define NS    128
#define NT    63
#define N3U   1536
#define BT    (NB*NT)

__device__ float g_MX[NT*NB*N3U];
__device__ float g_KEYS[NB*NS*UNITS];
__device__ float g_WTK[N3U*UNITS];
__device__ float g_WTR[N3U*UNITS];
__device__ float g_WqT[UNITS*UNITS];
__device__ float g_WaT[UNITS*2*UNITS];
__device__ float g_h[2][NB*UNITS];
__device__ float g_attn[2][NB*UNITS];
__device__ float g_pq[NB*UNITS];
__device__ float g_cat[NB*2*UNITS];
__device__ float g_attn_all[BT*UNITS];
__device__ int   g_rowtok[BT];

__device__ __forceinline__ float sigmoid_f(float x) {
    return 1.0f / (1.0f + __expf(-x));
}

// ------------------------- prep: transposes + init ---------------------------
__global__ void prep_kernel(const int* __restrict__ x, const float* __restrict__ enc,
                            const float* __restrict__ Kk, const float* __restrict__ Rk,
                            const float* __restrict__ Wq, const float* __restrict__ Wa)
{
    const int NWTK = N3U*UNITS, NWQ = UNITS*UNITS, NWA = UNITS*2*UNITS;
    const int total = NWTK + NWTK + NWQ + NWA + BT + NB*UNITS + NB*UNITS;
    for (int i = blockIdx.x*blockDim.x + threadIdx.x; i < total; i += gridDim.x*blockDim.x) {
        int j = i;
        if (j < NWTK) { int n = j >> 9, k = j & 511; g_WTK[j] = Kk[(EMB + k)*N3U + n]; continue; }
        j -= NWTK;
        if (j < NWTK) { int n = j >> 9, k = j & 511; g_WTR[j] = Rk[k*N3U + n]; continue; }
        j -= NWTK;
        if (j < NWQ)  { int u = j >> 9, k = j & 511; g_WqT[j] = Wq[k*UNITS + u]; continue; }
        j -= NWQ;
        if (j < NWA)  { int u = j >> 10, k = j & 1023; g_WaT[j] = Wa[k*UNITS + u]; continue; }
        j -= NWA;
        if (j < BT)   { int t = j >> 5, b = j & 31; g_rowtok[j] = x[b*NT + t]; continue; }
        j -= BT;
        if (j < NB*UNITS) { g_h[0][j] = enc[j]; continue; }
        j -= NB*UNITS;
        g_attn[0][j] = 0.0f;
    }
}

// ---------------- generic 64x64 tiled SGEMM, optional gather/bias ------------
__global__ void sgemm64(const float* __restrict__ A, int lda,
                        const float* __restrict__ B, int ldb,
                        float* __restrict__ C, int ldc,
                        int M, int N, int K,
                        const float* __restrict__ bias,
                        const int* __restrict__ gather)
{
    __shared__ float As[16][64];
    __shared__ float Bs[16][64];
    const int t = threadIdx.x;                 // 256 threads
    const int row0 = blockIdx.y << 6;
    const int col0 = blockIdx.x << 6;
    const int a_row = t >> 2, a_k = (t & 3) << 2;
    const int b_k = t >> 4, b_c = (t & 15) << 2;
    const int ty = t >> 4, tx = t & 15;

    float acc[4][4];
    #pragma unroll
    for (int i = 0; i < 4; i++)
        #pragma unroll
        for (int j = 0; j < 4; j++) acc[i][j] = 0.0f;

    const float* Ar = nullptr;
    {
        int ar = row0 + a_row;
        if (ar < M) {
            long r = gather ? (long)gather[ar] : (long)ar;
            Ar = A + r * (long)lda;
        }
    }

    for (int k0 = 0; k0 < K; k0 += 16) {
        float4 av = make_float4(0.f, 0.f, 0.f, 0.f);
        if (Ar) av = *(const float4*)(Ar + k0 + a_k);
        As[a_k + 0][a_row] = av.x;
        As[a_k + 1][a_row] = av.y;
        As[a_k + 2][a_row] = av.z;
        As[a_k + 3][a_row] = av.w;
        *(float4*)&Bs[b_k][b_c] = *(const float4*)(B + (long)(k0 + b_k) * ldb + col0 + b_c);
        __syncthreads();
        #pragma unroll
        for (int k = 0; k < 16; k++) {
            float4 a4 = *(const float4*)&As[k][ty << 2];
            float4 b4 = *(const float4*)&Bs[k][tx << 2];
            float a[4] = {a4.x, a4.y, a4.z, a4.w};
            float b[4] = {b4.x, b4.y, b4.z, b4.w};
            #pragma unroll
            for (int i = 0; i < 4; i++)
                #pragma unroll
                for (int j = 0; j < 4; j++)
                    acc[i][j] = fmaf(a[i], b[j], acc[i][j]);
        }
        __syncthreads();
    }

    #pragma unroll
    for (int i = 0; i < 4; i++) {
        int r = row0 + (ty << 2) + i;
        if (r < M) {
            int c = col0 + (tx << 2);
            float4 o;
            o.x = acc[i][0] + (bias ? bias[c + 0] : 0.f);
            o.y = acc[i][1] + (bias ? bias[c + 1] : 0.f);
            o.z = acc[i][2] + (bias ? bias[c + 2] : 0.f);
            o.w = acc[i][3] + (bias ? bias[c + 3] : 0.f);
            *(float4*)(C + (long)r * ldc + c) = o;
        }
    }
}

// ------------------------- per-step GRU gate kernel --------------------------
// 128 blocks x 128 threads; warp = output column u, lane = batch b.
__global__ void gru_step(int t, int par, const float* __restrict__ gbias)
{
    __shared__ float Ash[64][33];
    __shared__ float Hsh[64][33];
    const int tid = threadIdx.x, wid = tid >> 5, lane = tid & 31;
    const int u = (blockIdx.x << 2) + wid;
    const float* __restrict__ ain = g_attn[par];
    const float* __restrict__ hin = g_h[par];
    const float* __restrict__ wxz = g_WTK + (long)u * UNITS;
    const float* __restrict__ wxr = g_WTK + (long)(u + 512) * UNITS;
    const float* __restrict__ wxh = g_WTK + (long)(u + 1024) * UNITS;
    const float* __restrict__ whz = g_WTR + (long)u * UNITS;
    const float* __restrict__ whr = g_WTR + (long)(u + 512) * UNITS;
    const float* __restrict__ whh = g_WTR + (long)(u + 1024) * UNITS;

    float xz = 0.f, xr = 0.f, xh = 0.f, hz = 0.f, hr = 0.f, hhr = 0.f;

    for (int k0 = 0; k0 < UNITS; k0 += 64) {
        #pragma unroll
        for (int i = 0; i < 4; i++) {
            int fl = tid + (i << 7);
            int b = fl >> 4, kq = (fl & 15) << 2;
            float4 av = *(const float4*)(ain + (b << 9) + k0 + kq);
            Ash[kq + 0][b] = av.x; Ash[kq + 1][b] = av.y;
            Ash[kq + 2][b] = av.z; Ash[kq + 3][b] = av.w;
            float4 hv = *(const float4*)(hin + (b << 9) + k0 + kq);
            Hsh[kq + 0][b] = hv.x; Hsh[kq + 1][b] = hv.y;
            Hsh[kq + 2][b] = hv.z; Hsh[kq + 3][b] = hv.w;
        }
        __syncthreads();
        #pragma unroll
        for (int kk = 0; kk < 64; kk += 4) {
            float4 w0 = *(const float4*)(wxz + k0 + kk);
            float4 w1 = *(const float4*)(wxr + k0 + kk);
            float4 w2 = *(const float4*)(wxh + k0 + kk);
            float4 w3 = *(const float4*)(whz + k0 + kk);
            float4 w4 = *(const float4*)(whr + k0 + kk);
            float4 w5 = *(const float4*)(whh + k0 + kk);
            float a0 = Ash[kk + 0][lane], a1 = Ash[kk + 1][lane];
            float a2 = Ash[kk + 2][lane], a3 = Ash[kk + 3][lane];
            float h0 = Hsh[kk + 0][lane], h1 = Hsh[kk + 1][lane];
            float h2 = Hsh[kk + 2][lane], h3 = Hsh[kk + 3][lane];
            xz = fmaf(a0, w0.x, xz); xz = fmaf(a1, w0.y, xz); xz = fmaf(a2, w0.z, xz); xz = fmaf(a3, w0.w, xz);
            xr = fmaf(a0, w1.x, xr); xr = fmaf(a1, w1.y, xr); xr = fmaf(a2, w1.z, xr); xr = fmaf(a3, w1.w, xr);
            xh = fmaf(a0, w2.x, xh); xh = fmaf(a1, w2.y, xh); xh = fmaf(a2, w2.z, xh); xh = fmaf(a3, w2.w, xh);
            hz = fmaf(h0, w3.x, hz); hz = fmaf(h1, w3.y, hz); hz = fmaf(h2, w3.z, hz); hz = fmaf(h3, w3.w, hz);
            hr = fmaf(h0, w4.x, hr); hr = fmaf(h1, w4.y, hr); hr = fmaf(h2, w4.z, hr); hr = fmaf(h3, w4.w, hr);
            hhr = fmaf(h0, w5.x, hhr); hhr = fmaf(h1, w5.y, hhr); hhr = fmaf(h2, w5.z, hhr); hhr = fmaf(h3, w5.w, hhr);
        }
        __syncthreads();
    }

    const float* mx = g_MX + ((long)(t << 5) + lane) * N3U;   // already has bias0
    float z = sigmoid_f(mx[u]       + xz + hz + gbias[N3U + u]);
    float r = sigmoid_f(mx[u + 512] + xr + hr + gbias[N3U + 512 + u]);
    float hc = tanhf(mx[u + 1024] + xh + r * (hhr + gbias[N3U + 1024 + u]));
    float hold = hin[(lane << 9) + u];
    g_h[par ^ 1][(lane << 9) + u] = z * hold + (1.0f - z) * hc;
}

// -------- batched matvec: out[b*512+u] = in[b*K:] . WT[u*K:] -----------------
__global__ void smallmm(const float* __restrict__ in, int K,
                        const float* __restrict__ WT,
                        float* __restrict__ out,
                        float* __restrict__ out2, int stride2)
{
    __shared__ float sh[64][33];
    const int tid = threadIdx.x, wid = tid >> 5, lane = tid & 31;
    const int u = (blockIdx.x << 2) + wid;
    const float* __restrict__ w = WT + (long)u * K;
    float a0 = 0.f, a1 = 0.f, a2 = 0.f, a3 = 0.f;

    for (int k0 = 0; k0 < K; k0 += 64) {
        #pragma unroll
        for (int i = 0; i < 4; i++) {
            int fl = tid + (i << 7);
            int b = fl >> 4, kq = (fl & 15) << 2;
            float4 v = *(const float4*)(in + (long)b * K + k0 + kq);
            sh[kq + 0][b] = v.x; sh[kq + 1][b] = v.y;
            sh[kq + 2][b] = v.z; sh[kq + 3][b] = v.w;
        }
        __syncthreads();
        #pragma unroll
        for (int kk = 0; kk < 64; kk += 16) {
            float4 w0 = *(const float4*)(w + k0 + kk);
            float4 w1 = *(const float4*)(w + k0 + kk + 4);
            float4 w2 = *(const float4*)(w + k0 + kk + 8);
            float4 w3 = *(const float4*)(w + k0 + kk + 12);
            a0 = fmaf(sh[kk + 0][lane], w0.x, a0); a0 = fmaf(sh[kk + 1][lane], w0.y, a0);
            a0 = fmaf(sh[kk + 2][lane], w0.z, a0); a0 = fmaf(sh[kk + 3][lane], w0.w, a0);
            a1 = fmaf(sh[kk + 4][lane], w1.x, a1); a1 = fmaf(sh[kk + 5][lane], w1.y, a1);
            a1 = fmaf(sh[kk + 6][lane], w1.z, a1); a1 = fmaf(sh[kk + 7][lane], w1.w, a1);
            a2 = fmaf(sh[kk + 8][lane], w2.x, a2); a2 = fmaf(sh[kk + 9][lane], w2.y, a2);
            a2 = fmaf(sh[kk + 10][lane], w2.z, a2); a2 = fmaf(sh[kk + 11][lane], w2.w, a2);
            a3 = fmaf(sh[kk + 12][lane], w3.x, a3); a3 = fmaf(sh[kk + 13][lane], w3.y, a3);
            a3 = fmaf(sh[kk + 14][lane], w3.z, a3); a3 = fmaf(sh[kk + 15][lane], w3.w, a3);
        }
        __syncthreads();
    }
    float acc = (a0 + a1) + (a2 + a3);
    out[(lane << 9) + u] = acc;
    if (out2) out2[(long)lane * stride2 + u] = acc;
}

// ---------------- attention: scores -> softmax -> context -> cat -------------
// 32 blocks (one per batch) x 256 threads.
__global__ void att_step(int npar, const float* __restrict__ v_att,
                         const float* __restrict__ memory)
{
    __shared__ float pqs[UNITS];
    __shared__ float vsh[UNITS];
    __shared__ float sc[NS];
    __shared__ float red[20];
    const int b = blockIdx.x, tid = threadIdx.x;
    const int wid = tid >> 5, lane = tid & 31;

    const float* __restrict__ pq = g_pq + b * UNITS;
    for (int i = tid; i < UNITS; i += 256) { pqs[i] = pq[i]; vsh[i] = v_att[i]; }
    __syncthreads();

    const float* __restrict__ keysb = g_KEYS + (long)b * NS * UNITS;
    for (int si = 0; si < 16; si++) {
        int s = wid * 16 + si;
        const float* kr = keysb + s * UNITS;
        float acc = 0.f;
        #pragma unroll 4
        for (int u = lane; u < UNITS; u += 32)
            acc += vsh[u] * tanhf(kr[u] + pqs[u]);
        #pragma unroll
        for (int off = 16; off; off >>= 1) acc += __shfl_xor_sync(0xffffffffu, acc, off);
        if (lane == 0) sc[s] = acc;
    }
    __syncthreads();

    // softmax over NS=128
    float v = (tid < NS) ? sc[tid] : -1e30f;
    #pragma unroll
    for (int off = 16; off; off >>= 1) v = fmaxf(v, __shfl_xor_sync(0xffffffffu, v, off));
    if (lane == 0) red[wid] = v;
    __syncthreads();
    if (tid == 0) {
        float m = red[0];
        for (int i = 1; i < 8; i++) m = fmaxf(m, red[i]);
        red[16] = m;
    }
    __syncthreads();
    float m = red[16];
    float e = (tid < NS) ? __expf(sc[tid] - m) : 0.f;
    if (tid < NS) sc[tid] = e;
    float ss = e;
    #pragma unroll
    for (int off = 16; off; off >>= 1) ss += __shfl_xor_sync(0xffffffffu, ss, off);
    if (lane == 0) red[wid] = ss;
    __syncthreads();
    if (tid == 0) {
        float s = 0.f;
        for (int i = 0; i < 8; i++) s += red[i];
        red[17] = 1.0f / s;
    }
    __syncthreads();
    float inv = red[17];
    if (tid < NS) sc[tid] *= inv;
    __syncthreads();

    // context + concat
    const float* __restrict__ memb = memory + (long)b * NS * UNITS;
    const float* __restrict__ hb = g_h[npar] + b * UNITS;
    float* catb = g_cat + b * 2 * UNITS;
    for (int u = tid; u < UNITS; u += 256) {
        float acc = 0.f;
        #pragma unroll 4
        for (int s = 0; s < NS; s++)
            acc = fmaf(sc[s], memb[s * UNITS + u], acc);
        catb[UNITS + u] = acc;
        catb[u] = hb[u];
    }
}

extern "C" void kernel_launch(void* const* d_in, const int* in_sizes, int n_in,
                              void* d_out, int out_size) {
    const int*   x      = (const int*)d_in[0];
    const float* enc    = (const float*)d_in[1];
    const float* memory = (const float*)d_in[2];
    const float* E      = (const float*)d_in[3];
    const float* Kk     = (const float*)d_in[4];
    const float* Rk     = (const float*)d_in[5];
    const float* gbias  = (const float*)d_in[6];
    const float* Wq     = (const float*)d_in[7];
    const float* Wk     = (const float*)d_in[8];
    const float* v_att  = (const float*)d_in[9];
    const float* Wa     = (const float*)d_in[10];
    const float* Wo     = (const float*)d_in[11];
    const float* bo     = (const float*)d_in[12];
    float* out = (float*)d_out;

    void *pKEYS, *pMX, *pAll, *pRT, *pH, *pAttn, *pPq, *pCat, *pWqT, *pWaT;
    cudaGetSymbolAddress(&pKEYS, g_KEYS);
    cudaGetSymbolAddress(&pMX,   g_MX);
    cudaGetSymbolAddress(&pAll,  g_attn_all);
    cudaGetSymbolAddress(&pRT,   g_rowtok);
    cudaGetSymbolAddress(&pH,    g_h);
    cudaGetSymbolAddress(&pAttn, g_attn);
    cudaGetSymbolAddress(&pPq,   g_pq);
    cudaGetSymbolAddress(&pCat,  g_cat);
    cudaGetSymbolAddress(&pWqT,  g_WqT);
    cudaGetSymbolAddress(&pWaT,  g_WaT);

    prep_kernel<<<256, 256>>>(x, enc, Kk, Rk, Wq, Wa);

    // keys = memory @ Wk : [4096,512] x [512,512]
    sgemm64<<<dim3(8, 64), 256>>>(memory, UNITS, Wk, UNITS,
                                  (float*)pKEYS, UNITS, NB*NS, UNITS, UNITS,
                                  nullptr, nullptr);
    // MX = E[rowtok] @ K_kernel[:256,:] + bias0 : [2016,256] x [256,1536]
    sgemm64<<<dim3(24, 32), 256>>>(E, EMB, Kk, N3U,
                                   (float*)pMX, N3U, BT, N3U, EMB,
                                   gbias, (const int*)pRT);

    for (int t = 0; t < NT; t++) {
        int par = t & 1;
        int npar = par ^ 1;
        gru_step<<<128, 128>>>(t, par, gbias);
        smallmm<<<128, 128>>>((const float*)pH + npar * NB * UNITS, UNITS,
                              (const float*)pWqT, (float*)pPq, nullptr, 0);
        att_step<<<32, 256>>>(npar, v_att, memory);
        smallmm<<<128, 128>>>((const float*)pCat, 2 * UNITS,
                              (const float*)pWaT,
                              (float*)pAttn + npar * NB * UNITS,
                              (float*)pAll + t * UNITS, NT * UNITS);
    }

    // logits = attn_all @ Wo + bo : [2016,512] x [512,32000]
    sgemm64<<<dim3(VOCAB / 64, 32), 256>>>((const float*)pAll, UNITS, Wo, VOCAB,
                                           out, VOCAB, BT, VOCAB, UNITS,
                                           bo, nullptr);
}

// round 9
// speedup vs baseline: 1.6669x; 1.6669x over previous
#include <cuda_runtime.h>
#include <cuda_bf16.h>
#include <math.h>

#define VOCAB 32000
#define EMB   256
#define UNITS 512
#define NB    32
#define NS    128
#define NT    63
#define N3U   1536
#define BT    (NB*NT)

__device__ float g_MX[NT*NB*N3U];
__device__ float g_KEYS[NB*NS*UNITS];
__device__ float g_WTK[N3U*UNITS];
__device__ float g_WTR[N3U*UNITS];
__device__ float g_WqT[UNITS*UNITS];
__device__ float g_WaT[UNITS*2*UNITS];
__device__ float g_h[2][NB*UNITS];
__device__ float g_attn[2][NB*UNITS];
__device__ float g_cat[NB*2*UNITS];
__device__ float g_attn_all[BT*UNITS];
__device__ int   g_rowtok[BT];

__device__ __forceinline__ float sigmoid_f(float x) {
    return 1.0f / (1.0f + __expf(-x));
}
__device__ __forceinline__ float tanh_fast(float x) {
    float y; asm("tanh.approx.f32 %0, %1;" : "=f"(y) : "f"(x)); return y;
}

// ------------------------- prep: transposes + init ---------------------------
__global__ void prep_kernel(const int* __restrict__ x, const float* __restrict__ enc,
                            const float* __restrict__ Kk, const float* __restrict__ Rk,
                            const float* __restrict__ Wq, const float* __restrict__ Wa)
{
    const int NWTK = N3U*UNITS, NWQ = UNITS*UNITS, NWA = UNITS*2*UNITS;
    const int total = NWTK + NWTK + NWQ + NWA + BT + NB*UNITS + NB*UNITS;
    for (int i = blockIdx.x*blockDim.x + threadIdx.x; i < total; i += gridDim.x*blockDim.x) {
        int j = i;
        if (j < NWTK) { int n = j >> 9, k = j & 511; g_WTK[j] = Kk[(EMB + k)*N3U + n]; continue; }
        j -= NWTK;
        if (j < NWTK) { int n = j >> 9, k = j & 511; g_WTR[j] = Rk[k*N3U + n]; continue; }
        j -= NWTK;
        if (j < NWQ)  { int u = j >> 9, k = j & 511; g_WqT[j] = Wq[k*UNITS + u]; continue; }
        j -= NWQ;
        if (j < NWA)  { int u = j >> 10, k = j & 1023; g_WaT[j] = Wa[k*UNITS + u]; continue; }
        j -= NWA;
        if (j < BT)   { int t = j >> 5, b = j & 31; g_rowtok[j] = x[b*NT + t]; continue; }
        j -= BT;
        if (j < NB*UNITS) { g_h[0][j] = enc[j]; continue; }
        j -= NB*UNITS;
        g_attn[0][j] = 0.0f;
    }
}

// ---------------- generic 64x64 tiled SGEMM, optional gather/bias ------------
__global__ void sgemm64(const float* __restrict__ A, int lda,
                        const float* __restrict__ B, int ldb,
                        float* __restrict__ C, int ldc,
                        int M, int N, int K,
                        const float* __restrict__ bias,
                        const int* __restrict__ gather)
{
    __shared__ float As[16][64];
    __shared__ float Bs[16][64];
    const int t = threadIdx.x;                 // 256 threads
    const int row0 = blockIdx.y << 6;
    const int col0 = blockIdx.x << 6;
    const int a_row = t >> 2, a_k = (t & 3) << 2;
    const int b_k = t >> 4, b_c = (t & 15) << 2;
    const int ty = t >> 4, tx = t & 15;

    float acc[4][4];
    #pragma unroll
    for (int i = 0; i < 4; i++)
        #pragma unroll
        for (int j = 0; j < 4; j++) acc[i][j] = 0.0f;

    const float* Ar = nullptr;
    {
        int ar = row0 + a_row;
        if (ar < M) {
            long r = gather ? (long)gather[ar] : (long)ar;
            Ar = A + r * (long)lda;
        }
    }

    for (int k0 = 0; k0 < K; k0 += 16) {
        float4 av = make_float4(0.f, 0.f, 0.f, 0.f);
        if (Ar) av = *(const float4*)(Ar + k0 + a_k);
        As[a_k + 0][a_row] = av.x;
        As[a_k + 1][a_row] = av.y;
        As[a_k + 2][a_row] = av.z;
        As[a_k + 3][a_row] = av.w;
        *(float4*)&Bs[b_k][b_c] = *(const float4*)(B + (long)(k0 + b_k) * ldb + col0 + b_c);
        __syncthreads();
        #pragma unroll
        for (int k = 0; k < 16; k++) {
            float4 a4 = *(const float4*)&As[k][ty << 2];
            float4 b4 = *(const float4*)&Bs[k][tx << 2];
            float a[4] = {a4.x, a4.y, a4.z, a4.w};
            float b[4] = {b4.x, b4.y, b4.z, b4.w};
            #pragma unroll
            for (int i = 0; i < 4; i++)
                #pragma unroll
                for (int j = 0; j < 4; j++)
                    acc[i][j] = fmaf(a[i], b[j], acc[i][j]);
        }
        __syncthreads();
    }

    #pragma unroll
    for (int i = 0; i < 4; i++) {
        int r = row0 + (ty << 2) + i;
        if (r < M) {
            int c = col0 + (tx << 2);
            float4 o;
            o.x = acc[i][0] + (bias ? bias[c + 0] : 0.f);
            o.y = acc[i][1] + (bias ? bias[c + 1] : 0.f);
            o.z = acc[i][2] + (bias ? bias[c + 2] : 0.f);
            o.w = acc[i][3] + (bias ? bias[c + 3] : 0.f);
            *(float4*)(C + (long)r * ldc + c) = o;
        }
    }
}

// ------------------------- per-step GRU gate kernel --------------------------
// 128 blocks x 256 threads (8 warps). Warp = (u_local 0..3, gate-family 0..1).
// gf=0 computes xz,xr,xh from attn; gf=1 computes hz,hr,hhr from h. Shared reduce.
__global__ void gru_step(int t, int par, const float* __restrict__ gbias)
{
    __shared__ float Ash[64][33];
    __shared__ float Hsh[64][33];
    __shared__ float red[4][3][32];
    const int tid = threadIdx.x, w = tid >> 5, lane = tid & 31;
    const int ul = w >> 1, gf = w & 1;
    const int u = (blockIdx.x << 2) + ul;
    const float* __restrict__ ain = g_attn[par];
    const float* __restrict__ hin = g_h[par];

    const float* __restrict__ wbase = gf ? g_WTR : g_WTK;
    const float* __restrict__ w0 = wbase + (long)u * UNITS;
    const float* __restrict__ w1 = wbase + (long)(u + 512) * UNITS;
    const float* __restrict__ w2 = wbase + (long)(u + 1024) * UNITS;
    const float* sh = gf ? &Hsh[0][0] : &Ash[0][0];

    float a0c = 0.f, a1c = 0.f, a2c = 0.f;

    for (int c = 0; c < 8; c++) {
        const int k0 = c << 6;
        __syncthreads();
        #pragma unroll
        for (int i = 0; i < 4; i++) {
            int f = tid + (i << 8);            // 0..1023
            int m = f >> 9, r = f & 511;
            int b = r >> 4, kq = (r & 15) << 2;
            const float* src = m ? hin : ain;
            float4 v = *(const float4*)(src + (b << 9) + k0 + kq);
            float* dst = m ? &Hsh[0][0] : &Ash[0][0];
            dst[(kq + 0) * 33 + b] = v.x;
            dst[(kq + 1) * 33 + b] = v.y;
            dst[(kq + 2) * 33 + b] = v.z;
            dst[(kq + 3) * 33 + b] = v.w;
        }
        __syncthreads();
        #pragma unroll
        for (int kk = 0; kk < 64; kk += 4) {
            float4 v0 = *(const float4*)(w0 + k0 + kk);
            float4 v1 = *(const float4*)(w1 + k0 + kk);
            float4 v2 = *(const float4*)(w2 + k0 + kk);
            float x0 = sh[(kk + 0) * 33 + lane];
            float x1 = sh[(kk + 1) * 33 + lane];
            float x2 = sh[(kk + 2) * 33 + lane];
            float x3 = sh[(kk + 3) * 33 + lane];
            a0c = fmaf(x0, v0.x, a0c); a1c = fmaf(x0, v1.x, a1c); a2c = fmaf(x0, v2.x, a2c);
            a0c = fmaf(x1, v0.y, a0c); a1c = fmaf(x1, v1.y, a1c); a2c = fmaf(x1, v2.y, a2c);
            a0c = fmaf(x2, v0.z, a0c); a1c = fmaf(x2, v1.z, a1c); a2c = fmaf(x2, v2.z, a2c);
            a0c = fmaf(x3, v0.w, a0c); a1c = fmaf(x3, v1.w, a1c); a2c = fmaf(x3, v2.w, a2c);
        }
    }

    if (gf) {
        red[ul][0][lane] = a0c;   // hz
        red[ul][1][lane] = a1c;   // hr
        red[ul][2][lane] = a2c;   // hhr
    }
    __syncthreads();
    if (!gf) {
        float hz  = red[ul][0][lane];
        float hr  = red[ul][1][lane];
        float hhr = red[ul][2][lane];
        const float* mx = g_MX + ((long)(t << 5) + lane) * N3U;   // has bias0
        float z  = sigmoid_f(mx[u]        + a0c + hz + gbias[N3U + u]);
        float r  = sigmoid_f(mx[u + 512]  + a1c + hr + gbias[N3U + 512 + u]);
        float hc = tanhf(mx[u + 1024] + a2c + r * (hhr + gbias[N3U + 1024 + u]));
        float hold = hin[(lane << 9) + u];
        g_h[par ^ 1][(lane << 9) + u] = z * hold + (1.0f - z) * hc;
    }
}

// -------- attention step (pq fused): 32 blocks x 512 threads -----------------
__global__ void att_step(int npar, const float* __restrict__ v_att,
                         const float* __restrict__ memory)
{
    __shared__ float hs[UNITS];
    __shared__ float pqs[UNITS];
    __shared__ float vsh[UNITS];
    __shared__ float sc[NS];
    __shared__ float red[20];
    const int b = blockIdx.x, tid = threadIdx.x;
    const int w = tid >> 5, lane = tid & 31;

    const float* __restrict__ hb = g_h[npar] + b * UNITS;
    hs[tid]  = hb[tid];
    vsh[tid] = v_att[tid];
    __syncthreads();

    // pq[u] = h . WqT[u]   (16 warps x 32 u each)
    {
        #pragma unroll 1
        for (int uu = 0; uu < 32; uu++) {
            int u = (w << 5) + uu;
            const float* __restrict__ wr = g_WqT + (long)u * UNITS;
            float acc = 0.f;
            #pragma unroll
            for (int j = 0; j < 4; j++) {
                float4 wv = *(const float4*)(wr + (j << 7) + (lane << 2));
                float4 hv = *(const float4*)(hs + (j << 7) + (lane << 2));
                acc = fmaf(hv.x, wv.x, acc);
                acc = fmaf(hv.y, wv.y, acc);
                acc = fmaf(hv.z, wv.z, acc);
                acc = fmaf(hv.w, wv.w, acc);
            }
            #pragma unroll
            for (int off = 16; off; off >>= 1) acc += __shfl_xor_sync(0xffffffffu, acc, off);
            if (lane == 0) pqs[u] = acc;
        }
    }
    __syncthreads();

    // scores[s] = v . tanh(keys[s] + pq)   (16 warps x 8 s each)
    {
        const float* __restrict__ keysb = g_KEYS + (long)b * NS * UNITS;
        #pragma unroll 1
        for (int si = 0; si < 8; si++) {
            int s = (w << 3) + si;
            const float* kr = keysb + s * UNITS;
            float acc = 0.f;
            #pragma unroll
            for (int j = 0; j < 4; j++) {
                float4 kv = *(const float4*)(kr + (j << 7) + (lane << 2));
                float4 pv = *(const float4*)(pqs + (j << 7) + (lane << 2));
                float4 vv = *(const float4*)(vsh + (j << 7) + (lane << 2));
                acc = fmaf(vv.x, tanh_fast(kv.x + pv.x), acc);
                acc = fmaf(vv.y, tanh_fast(kv.y + pv.y), acc);
                acc = fmaf(vv.z, tanh_fast(kv.z + pv.z), acc);
                acc = fmaf(vv.w, tanh_fast(kv.w + pv.w), acc);
            }
            #pragma unroll
            for (int off = 16; off; off >>= 1) acc += __shfl_xor_sync(0xffffffffu, acc, off);
            if (lane == 0) sc[s] = acc;
        }
    }
    __syncthreads();

    // softmax over NS=128
    float v = (tid < NS) ? sc[tid] : -1e30f;
    #pragma unroll
    for (int off = 16; off; off >>= 1) v = fmaxf(v, __shfl_xor_sync(0xffffffffu, v, off));
    if (lane == 0) red[w] = v;
    __syncthreads();
    if (tid == 0) {
        float m = red[0];
        for (int i = 1; i < 16; i++) m = fmaxf(m, red[i]);
        red[16] = m;
    }
    __syncthreads();
    float m = red[16];
    float e = (tid < NS) ? __expf(sc[tid] - m) : 0.f;
    float ss = e;
    #pragma unroll
    for (int off = 16; off; off >>= 1) ss += __shfl_xor_sync(0xffffffffu, ss, off);
    if (lane == 0) red[w] = ss;
    __syncthreads();
    if (tid == 0) {
        float s = 0.f;
        for (int i = 0; i < 16; i++) s += red[i];
        red[17] = 1.0f / s;
    }
    __syncthreads();
    if (tid < NS) sc[tid] = e * red[17];
    __syncthreads();

    // context + concat  (u = tid)
    const float* __restrict__ memb = memory + (long)b * NS * UNITS;
    float* catb = g_cat + b * 2 * UNITS;
    float acc = 0.f;
    #pragma unroll 8
    for (int s = 0; s < NS; s++)
        acc = fmaf(sc[s], memb[s * UNITS + tid], acc);
    catb[UNITS + tid] = acc;
    catb[tid] = hs[tid];
}

// -------- Wa matvec: attn_new[b][u] = cat[b][:1024] . WaT[u][:1024] ----------
// 128 blocks x 256 threads (8 warps). Warp = (u_local 0..3, k-half 0..1).
__global__ void wa_step(int t, int npar)
{
    __shared__ float Csh[2][64][33];
    __shared__ float red[4][32];
    const int tid = threadIdx.x, w = tid >> 5, lane = tid & 31;
    const int ul = w >> 1, kh = w & 1;
    const int u = (blockIdx.x << 2) + ul;
    const float* __restrict__ wr = g_WaT + (long)u * (2 * UNITS) + kh * UNITS;
    const float* sh = &Csh[kh][0][0];

    float acc = 0.f;
    for (int c = 0; c < 8; c++) {
        const int k0 = c << 6;
        __syncthreads();
        #pragma unroll
        for (int i = 0; i < 4; i++) {
            int f = tid + (i << 8);
            int half = f >> 9, r = f & 511;
            int b = r >> 4, kq = (r & 15) << 2;
            float4 v = *(const float4*)(g_cat + b * (2 * UNITS) + half * UNITS + k0 + kq);
            Csh[half][kq + 0][b] = v.x;
            Csh[half][kq + 1][b] = v.y;
            Csh[half][kq + 2][b] = v.z;
            Csh[half][kq + 3][b] = v.w;
        }
        __syncthreads();
        #pragma unroll
        for (int kk = 0; kk < 64; kk += 4) {
            float4 wv = *(const float4*)(wr + k0 + kk);
            acc = fmaf(sh[(kk + 0) * 33 + lane], wv.x, acc);
            acc = fmaf(sh[(kk + 1) * 33 + lane], wv.y, acc);
            acc = fmaf(sh[(kk + 2) * 33 + lane], wv.z, acc);
            acc = fmaf(sh[(kk + 3) * 33 + lane], wv.w, acc);
        }
    }

    if (kh) red[ul][lane] = acc;
    __syncthreads();
    if (!kh) {
        float r = acc + red[ul][lane];
        g_attn[npar][(lane << 9) + u] = r;
        g_attn_all[((lane * NT + t) << 9) + u] = r;
    }
}

extern "C" void kernel_launch(void* const* d_in, const int* in_sizes, int n_in,
                              void* d_out, int out_size) {
    const int*   x      = (const int*)d_in[0];
    const float* enc    = (const float*)d_in[1];
    const float* memory = (const float*)d_in[2];
    const float* E      = (const float*)d_in[3];
    const float* Kk     = (const float*)d_in[4];
    const float* Rk     = (const float*)d_in[5];
    const float* gbias  = (const float*)d_in[6];
    const float* Wq     = (const float*)d_in[7];
    const float* Wk     = (const float*)d_in[8];
    const float* v_att  = (const float*)d_in[9];
    const float* Wa     = (const float*)d_in[10];
    const float* Wo     = (const float*)d_in[11];
    const float* bo     = (const float*)d_in[12];
    float* out = (float*)d_out;

    void *pKEYS, *pMX, *pAll, *pRT;
    cudaGetSymbolAddress(&pKEYS, g_KEYS);
    cudaGetSymbolAddress(&pMX,   g_MX);
    cudaGetSymbolAddress(&pAll,  g_attn_all);
    cudaGetSymbolAddress(&pRT,   g_rowtok);

    prep_kernel<<<256, 256>>>(x, enc, Kk, Rk, Wq, Wa);

    // keys = memory @ Wk : [4096,512] x [512,512]
    sgemm64<<<dim3(8, 64), 256>>>(memory, UNITS, Wk, UNITS,
                                  (float*)pKEYS, UNITS, NB*NS, UNITS, UNITS,
                                  nullptr, nullptr);
    // MX = E[rowtok] @ K_kernel[:256,:] + bias0 : [2016,256] x [256,1536]
    sgemm64<<<dim3(24, 32), 256>>>(E, EMB, Kk, N3U,
                                   (float*)pMX, N3U, BT, N3U, EMB,
                                   gbias, (const int*)pRT);

    for (int t = 0; t < NT; t++) {
        int par = t & 1;
        int npar = par ^ 1;
        gru_step<<<128, 256>>>(t, par, gbias);
        att_step<<<32, 512>>>(npar, v_att, memory);
        wa_step<<<128, 256>>>(t, npar);
    }

    // logits = attn_all @ Wo + bo : [2016,512] x [512,32000]
    sgemm64<<<dim3(VOCAB / 64, 32), 256>>>((const float*)pAll, UNITS, Wo, VOCAB,
                                           out, VOCAB, BT, VOCAB, UNITS,
                                           bo, nullptr);
}

// round 11
// speedup vs baseline: 2.0323x; 1.2192x over previous
#include <cuda_runtime.h>
#include <cuda_bf16.h>
#include <math.h>

#define VOCAB 32000
#define EMB   256
#define UNITS 512
#define NB    32
#define NS    128
#define NT    63
#define N3U   1536
#define BT    (NB*NT)

__device__ float  g_MX [NT*NB*N3U];      // [t*32+b][1536] gemm output
__device__ float  g_MXT[NT*N3U*NB];      // [t][j][b] transposed
__device__ float  g_KEYS[NB*NS*UNITS];
__device__ float  g_WTK[N3U*UNITS];
__device__ float  g_WTR[N3U*UNITS];
__device__ float  g_WqT[UNITS*UNITS];
__device__ float  g_WaT[UNITS*2*UNITS];
__device__ float4 g_hQ  [2][128*32];     // [k4][b] packed 4 consecutive k
__device__ float4 g_attnQ[2][128*32];
__device__ float  g_attn_all[BT*UNITS];
__device__ int    g_rowtok[BT];

__device__ __forceinline__ float sigmoid_f(float x) {
    return 1.0f / (1.0f + __expf(-x));
}
__device__ __forceinline__ float tanh_fast(float x) {
    float y; asm("tanh.approx.f32 %0, %1;" : "=f"(y) : "f"(x)); return y;
}

// ------------------------- prep: transposes + init ---------------------------
__global__ void prep_kernel(const int* __restrict__ x, const float* __restrict__ enc,
                            const float* __restrict__ Kk, const float* __restrict__ Rk,
                            const float* __restrict__ Wq, const float* __restrict__ Wa)
{
    const int NWTK = N3U*UNITS, NWQ = UNITS*UNITS, NWA = UNITS*2*UNITS;
    const int total = NWTK + NWTK + NWQ + NWA + BT + NB*UNITS + NB*UNITS;
    for (int i = blockIdx.x*blockDim.x + threadIdx.x; i < total; i += gridDim.x*blockDim.x) {
        int j = i;
        if (j < NWTK) { int n = j >> 9, k = j & 511; g_WTK[j] = Kk[(EMB + k)*N3U + n]; continue; }
        j -= NWTK;
        if (j < NWTK) { int n = j >> 9, k = j & 511; g_WTR[j] = Rk[k*N3U + n]; continue; }
        j -= NWTK;
        if (j < NWQ)  { int u = j >> 9, k = j & 511; g_WqT[j] = Wq[k*UNITS + u]; continue; }
        j -= NWQ;
        if (j < NWA)  { int u = j >> 10, k = j & 1023; g_WaT[j] = Wa[k*UNITS + u]; continue; }
        j -= NWA;
        if (j < BT)   { int t = j >> 5, b = j & 31; g_rowtok[j] = x[b*NT + t]; continue; }
        j -= BT;
        if (j < NB*UNITS) {
            int b = j >> 9, u = j & 511;
            ((float*)g_hQ[0])[(((u >> 2) << 5) + b) * 4 + (u & 3)] = enc[j];
            continue;
        }
        j -= NB*UNITS;
        ((float*)g_attnQ[0])[j] = 0.0f;
    }
}

// ---------------- MX transpose: [t*32+b][1536] -> [t][j][b] ------------------
__global__ void mxt_kernel()
{
    const int total = NT*N3U*NB;
    for (int i = blockIdx.x*blockDim.x + threadIdx.x; i < total; i += gridDim.x*blockDim.x) {
        int b = i & 31;
        int j = (i >> 5) % N3U;
        int t = i / (N3U * NB);
        g_MXT[i] = g_MX[((long)(t * 32 + b)) * N3U + j];
    }
}

// ---------------- generic 64x64 tiled SGEMM, optional gather/bias ------------
__global__ void sgemm64(const float* __restrict__ A, int lda,
                        const float* __restrict__ B, int ldb,
                        float* __restrict__ C, int ldc,
                        int M, int N, int K,
                        const float* __restrict__ bias,
                        const int* __restrict__ gather)
{
    __shared__ float As[16][64];
    __shared__ float Bs[16][64];
    const int t = threadIdx.x;
    const int row0 = blockIdx.y << 6;
    const int col0 = blockIdx.x << 6;
    const int a_row = t >> 2, a_k = (t & 3) << 2;
    const int b_k = t >> 4, b_c = (t & 15) << 2;
    const int ty = t >> 4, tx = t & 15;

    float acc[4][4];
    #pragma unroll
    for (int i = 0; i < 4; i++)
        #pragma unroll
        for (int j = 0; j < 4; j++) acc[i][j] = 0.0f;

    const float* Ar = nullptr;
    {
        int ar = row0 + a_row;
        if (ar < M) {
            long r = gather ? (long)gather[ar] : (long)ar;
            Ar = A + r * (long)lda;
        }
    }

    for (int k0 = 0; k0 < K; k0 += 16) {
        float4 av = make_float4(0.f, 0.f, 0.f, 0.f);
        if (Ar) av = *(const float4*)(Ar + k0 + a_k);
        As[a_k + 0][a_row] = av.x;
        As[a_k + 1][a_row] = av.y;
        As[a_k + 2][a_row] = av.z;
        As[a_k + 3][a_row] = av.w;
        *(float4*)&Bs[b_k][b_c] = *(const float4*)(B + (long)(k0 + b_k) * ldb + col0 + b_c);
        __syncthreads();
        #pragma unroll
        for (int k = 0; k < 16; k++) {
            float4 a4 = *(const float4*)&As[k][ty << 2];
            float4 b4 = *(const float4*)&Bs[k][tx << 2];
            float a[4] = {a4.x, a4.y, a4.z, a4.w};
            float b[4] = {b4.x, b4.y, b4.z, b4.w};
            #pragma unroll
            for (int i = 0; i < 4; i++)
                #pragma unroll
                for (int j = 0; j < 4; j++)
                    acc[i][j] = fmaf(a[i], b[j], acc[i][j]);
        }
        __syncthreads();
    }

    #pragma unroll
    for (int i = 0; i < 4; i++) {
        int r = row0 + (ty << 2) + i;
        if (r < M) {
            int c = col0 + (tx << 2);
            float4 o;
            o.x = acc[i][0] + (bias ? bias[c + 0] : 0.f);
            o.y = acc[i][1] + (bias ? bias[c + 1] : 0.f);
            o.z = acc[i][2] + (bias ? bias[c + 2] : 0.f);
            o.w = acc[i][3] + (bias ? bias[c + 3] : 0.f);
            *(float4*)(C + (long)r * ldc + c) = o;
        }
    }
}

// ---------------- 128x128 tiled SGEMM for the big logits GEMM ----------------
// C[M,VOCAB] = A[M,512] @ B[512,VOCAB] + bias.  8x8 per thread, 256 threads.
__global__ __launch_bounds__(256) void sgemm128(
    const float* __restrict__ A, const float* __restrict__ B,
    float* __restrict__ C, int M, const float* __restrict__ bias)
{
    __shared__ float As[8][128];
    __shared__ float Bs[8][128];
    const int t = threadIdx.x;
    const int row0 = blockIdx.y << 7;
    const int col0 = blockIdx.x << 7;
    const int ty = t >> 4, tx = t & 15;

    float acc[8][8];
    #pragma unroll
    for (int i = 0; i < 8; i++)
        #pragma unroll
        for (int j = 0; j < 8; j++) acc[i][j] = 0.0f;

    const int arow = row0 + (t >> 1);
    const bool aval = arow < M;
    const float* Ap = A + (long)arow * UNITS + ((t & 1) << 2);
    const float* Bp = B + (long)(t >> 5) * VOCAB + col0 + ((t & 31) << 2);
    const int a_kq = (t & 1) << 2, a_m = t >> 1;
    const int b_k = t >> 5, b_c = (t & 31) << 2;

    for (int k0 = 0; k0 < UNITS; k0 += 8) {
        float4 av = aval ? *(const float4*)(Ap + k0) : make_float4(0.f, 0.f, 0.f, 0.f);
        float4 bv = *(const float4*)(Bp + (long)k0 * VOCAB);
        __syncthreads();
        As[a_kq + 0][a_m] = av.x;
        As[a_kq + 1][a_m] = av.y;
        As[a_kq + 2][a_m] = av.z;
        As[a_kq + 3][a_m] = av.w;
        *(float4*)&Bs[b_k][b_c] = bv;
        __syncthreads();
        #pragma unroll
        for (int k = 0; k < 8; k++) {
            float4 a0 = *(const float4*)&As[k][ty << 3];
            float4 a1 = *(const float4*)&As[k][(ty << 3) + 4];
            float4 b0 = *(const float4*)&Bs[k][tx << 3];
            float4 b1 = *(const float4*)&Bs[k][(tx << 3) + 4];
            float a[8] = {a0.x, a0.y, a0.z, a0.w, a1.x, a1.y, a1.z, a1.w};
            float b[8] = {b0.x, b0.y, b0.z, b0.w, b1.x, b1.y, b1.z, b1.w};
            #pragma unroll
            for (int i = 0; i < 8; i++)
                #pragma unroll
                for (int j = 0; j < 8; j++)
                    acc[i][j] = fmaf(a[i], b[j], acc[i][j]);
        }
    }

    #pragma unroll
    for (int i = 0; i < 8; i++) {
        int r = row0 + (ty << 3) + i;
        if (r < M) {
            int c = col0 + (tx << 3);
            float4 o0, o1;
            o0.x = acc[i][0] + bias[c + 0]; o0.y = acc[i][1] + bias[c + 1];
            o0.z = acc[i][2] + bias[c + 2]; o0.w = acc[i][3] + bias[c + 3];
            o1.x = acc[i][4] + bias[c + 4]; o1.y = acc[i][5] + bias[c + 5];
            o1.z = acc[i][6] + bias[c + 6]; o1.w = acc[i][7] + bias[c + 7];
            *(float4*)(C + (long)r * VOCAB + c) = o0;
            *(float4*)(C + (long)r * VOCAB + c + 4) = o1;
        }
    }
}

// ------------------------- per-step GRU gate kernel --------------------------
// 256 blocks x 256 threads. Warp = (ul 0..1, gf 0..1, kh 0..1); u = blk*2+ul.
// Direct coalesced loads from k-grouped activations; no smem staging.
__global__ __launch_bounds__(256) void gru_step(int t, int par,
                                                const float* __restrict__ gbias)
{
    __shared__ float red[8][3][32];
    const int tid = threadIdx.x, w = tid >> 5, lane = tid & 31;
    const int ul = w >> 2, gf = (w >> 1) & 1, kh = w & 1;
    const int u = (blockIdx.x << 1) + ul;

    const float4* __restrict__ act = (gf ? g_hQ[par] : g_attnQ[par]) + (kh << 11);
    const float* __restrict__ wb = gf ? g_WTR : g_WTK;
    const float* __restrict__ w0 = wb + ((long)u << 9) + (kh << 8);
    const float* __restrict__ w1 = w0 + (512 << 9);
    const float* __restrict__ w2 = w1 + (512 << 9);

    float az = 0.f, ar = 0.f, ah = 0.f;
    #pragma unroll 8
    for (int k4 = 0; k4 < 64; k4++) {
        float4 a  = act[(k4 << 5) + lane];
        float4 vz = *(const float4*)(w0 + (k4 << 2));
        float4 vr = *(const float4*)(w1 + (k4 << 2));
        float4 vh = *(const float4*)(w2 + (k4 << 2));
        az = fmaf(a.x, vz.x, az); ar = fmaf(a.x, vr.x, ar); ah = fmaf(a.x, vh.x, ah);
        az = fmaf(a.y, vz.y, az); ar = fmaf(a.y, vr.y, ar); ah = fmaf(a.y, vh.y, ah);
        az = fmaf(a.z, vz.z, az); ar = fmaf(a.z, vr.z, ar); ah = fmaf(a.z, vh.z, ah);
        az = fmaf(a.w, vz.w, az); ar = fmaf(a.w, vr.w, ar); ah = fmaf(a.w, vh.w, ah);
    }
    red[w][0][lane] = az;
    red[w][1][lane] = ar;
    red[w][2][lane] = ah;
    __syncthreads();

    if ((w & 3) == 0) {
        const int base = w;                  // 0 or 4
        float xz  = red[base + 0][0][lane] + red[base + 1][0][lane];
        float hz  = red[base + 2][0][lane] + red[base + 3][0][lane];
        float xr  = red[base + 0][1][lane] + red[base + 1][1][lane];
        float hr  = red[base + 2][1][lane] + red[base + 3][1][lane];
        float xh  = red[base + 0][2][lane] + red[base + 1][2][lane];
        float hhr = red[base + 2][2][lane] + red[base + 3][2][lane];

        const float* mx = g_MXT + (long)t * N3U * NB;
        float mz = mx[((u)        << 5) + lane];
        float mr = mx[((u + 512)  << 5) + lane];
        float mh = mx[((u + 1024) << 5) + lane];

        float z  = sigmoid_f(mz + xz + hz + gbias[N3U + u]);
        float r  = sigmoid_f(mr + xr + hr + gbias[N3U + 512 + u]);
        float hh = tanhf(mh + xh + r * (hhr + gbias[N3U + 1024 + u]));

        const float* hp = (const float*)g_hQ[par];
        float hold = hp[((((u >> 2) << 5) + lane) << 2) + (u & 3)];
        float hnew = z * hold + (1.0f - z) * hh;
        ((float*)g_hQ[par ^ 1])[((((u >> 2) << 5) + lane) << 2) + (u & 3)] = hnew;
    }
}

// -------- fused attention + Wa: 32 blocks (per batch) x 1024 threads ---------
__global__ __launch_bounds__(1024) void att_wa_step(
    int t, int npar, const float* __restrict__ v_att,
    const float* __restrict__ memory)
{
    __shared__ float hs[UNITS];
    __shared__ float pqs[UNITS];
    __shared__ float vsh[UNITS];
    __shared__ float ctxs[UNITS];
    __shared__ float sc[NS];
    const int b = blockIdx.x, tid = threadIdx.x;
    const int w = tid >> 5, lane = tid & 31;

    if (tid < UNITS) {
        const float* hp = (const float*)g_hQ[npar];
        hs[tid]  = hp[((((tid >> 2) << 5) + b) << 2) + (tid & 3)];
        vsh[tid] = v_att[tid];
    }
    __syncthreads();

    // pq[u] = h . WqT[u]    (32 warps x 16 u each)
    {
        #pragma unroll 1
        for (int uu = 0; uu < 16; uu++) {
            int u = (w << 4) + uu;
            const float* __restrict__ wr = g_WqT + ((long)u << 9);
            float acc = 0.f;
            #pragma unroll
            for (int j = 0; j < 4; j++) {
                float4 wv = *(const float4*)(wr + (j << 7) + (lane << 2));
                float4 hv = *(const float4*)(hs + (j << 7) + (lane << 2));
                acc = fmaf(hv.x, wv.x, acc);
                acc = fmaf(hv.y, wv.y, acc);
                acc = fmaf(hv.z, wv.z, acc);
                acc = fmaf(hv.w, wv.w, acc);
            }
            #pragma unroll
            for (int off = 16; off; off >>= 1) acc += __shfl_xor_sync(0xffffffffu, acc, off);
            if (lane == 0) pqs[u] = acc;
        }
    }
    __syncthreads();

    // scores[s] = v . tanh(keys[s] + pq)    (32 warps x 4 s each)
    {
        const float* __restrict__ keysb = g_KEYS + (long)b * NS * UNITS;
        #pragma unroll 1
        for (int si = 0; si < 4; si++) {
            int s = (w << 2) + si;
            const float* kr = keysb + (s << 9);
            float acc = 0.f;
            #pragma unroll
            for (int j = 0; j < 4; j++) {
                float4 kv = *(const float4*)(kr + (j << 7) + (lane << 2));
                float4 pv = *(const float4*)(pqs + (j << 7) + (lane << 2));
                float4 vv = *(const float4*)(vsh + (j << 7) + (lane << 2));
                acc = fmaf(vv.x, tanh_fast(kv.x + pv.x), acc);
                acc = fmaf(vv.y, tanh_fast(kv.y + pv.y), acc);
                acc = fmaf(vv.z, tanh_fast(kv.z + pv.z), acc);
                acc = fmaf(vv.w, tanh_fast(kv.w + pv.w), acc);
            }
            #pragma unroll
            for (int off = 16; off; off >>= 1) acc += __shfl_xor_sync(0xffffffffu, acc, off);
            if (lane == 0) sc[s] = acc;
        }
    }
    __syncthreads();

    // softmax over 128 scores: single warp
    if (tid < 32) {
        float s0 = sc[tid], s1 = sc[tid + 32], s2 = sc[tid + 64], s3 = sc[tid + 96];
        float m = fmaxf(fmaxf(s0, s1), fmaxf(s2, s3));
        #pragma unroll
        for (int off = 16; off; off >>= 1) m = fmaxf(m, __shfl_xor_sync(0xffffffffu, m, off));
        float e0 = __expf(s0 - m), e1 = __expf(s1 - m);
        float e2 = __expf(s2 - m), e3 = __expf(s3 - m);
        float ss = (e0 + e1) + (e2 + e3);
        #pragma unroll
        for (int off = 16; off; off >>= 1) ss += __shfl_xor_sync(0xffffffffu, ss, off);
        float inv = 1.0f / ss;
        sc[tid] = e0 * inv; sc[tid + 32] = e1 * inv;
        sc[tid + 64] = e2 * inv; sc[tid + 96] = e3 * inv;
    }
    __syncthreads();

    // context[u] = sum_s align[s] * memory[b][s][u]   (split s over 2 halves)
    {
        const float* __restrict__ memb = memory + (long)b * NS * UNITS;
        int u = tid & 511, sh = tid >> 9;
        float acc = 0.f;
        const float* mp = memb + ((sh << 6) << 9) + u;
        const float* scp = sc + (sh << 6);
        #pragma unroll 8
        for (int s = 0; s < 64; s++)
            acc = fmaf(scp[s], mp[s << 9], acc);
        if (sh == 0) ctxs[u] = acc;
        __syncthreads();
        if (sh == 1) ctxs[u] += acc;
    }
    __syncthreads();

    // attn_new[u] = [h | ctx] . WaT[u]   (32 warps x 16 u each)
    {
        float* aq = (float*)g_attnQ[npar];
        #pragma unroll 1
        for (int uu = 0; uu < 16; uu++) {
            int u = (w << 4) + uu;
            const float* __restrict__ wr = g_WaT + ((long)u << 10);
            float acc = 0.f;
            #pragma unroll
            for (int j = 0; j < 4; j++) {
                float4 wv = *(const float4*)(wr + (j << 7) + (lane << 2));
                float4 xv = *(const float4*)(hs + (j << 7) + (lane << 2));
                acc = fmaf(xv.x, wv.x, acc);
                acc = fmaf(xv.y, wv.y, acc);
                acc = fmaf(xv.z, wv.z, acc);
                acc = fmaf(xv.w, wv.w, acc);
            }
            #pragma unroll
            for (int j = 0; j < 4; j++) {
                float4 wv = *(const float4*)(wr + 512 + (j << 7) + (lane << 2));
                float4 xv = *(const float4*)(ctxs + (j << 7) + (lane << 2));
                acc = fmaf(xv.x, wv.x, acc);
                acc = fmaf(xv.y, wv.y, acc);
                acc = fmaf(xv.z, wv.z, acc);
                acc = fmaf(xv.w, wv.w, acc);
            }
            #pragma unroll
            for (int off = 16; off; off >>= 1) acc += __shfl_xor_sync(0xffffffffu, acc, off);
            if (lane == 0) {
                aq[((((u >> 2) << 5) + b) << 2) + (u & 3)] = acc;
                g_attn_all[((long)(b * NT + t) << 9) + u] = acc;
            }
        }
    }
}

extern "C" void kernel_launch(void* const* d_in, const int* in_sizes, int n_in,
                              void* d_out, int out_size) {
    const int*   x      = (const int*)d_in[0];
    const float* enc    = (const float*)d_in[1];
    const float* memory = (const float*)d_in[2];
    const float* E      = (const float*)d_in[3];
    const float* Kk     = (const float*)d_in[4];
    const float* Rk     = (const float*)d_in[5];
    const float* gbias  = (const float*)d_in[6];
    const float* Wq     = (const float*)d_in[7];
    const float* Wk     = (const float*)d_in[8];
    const float* v_att  = (const float*)d_in[9];
    const float* Wa     = (const float*)d_in[10];
    const float* Wo     = (const float*)d_in[11];
    const float* bo     = (const float*)d_in[12];
    float* out = (float*)d_out;

    void *pKEYS, *pMX, *pAll, *pRT;
    cudaGetSymbolAddress(&pKEYS, g_KEYS);
    cudaGetSymbolAddress(&pMX,   g_MX);
    cudaGetSymbolAddress(&pAll,  g_attn_all);
    cudaGetSymbolAddress(&pRT,   g_rowtok);

    prep_kernel<<<256, 256>>>(x, enc, Kk, Rk, Wq, Wa);

    // keys = memory @ Wk : [4096,512] x [512,512]
    sgemm64<<<dim3(8, 64), 256>>>(memory, UNITS, Wk, UNITS,
                                  (float*)pKEYS, UNITS, NB*NS, UNITS, UNITS,
                                  nullptr, nullptr);
    // MX = E[rowtok] @ K_kernel[:256,:] + bias0 : [2016,256] x [256,1536]
    sgemm64<<<dim3(24, 32), 256>>>(E, EMB, Kk, N3U,
                                   (float*)pMX, N3U, BT, N3U, EMB,
                                   gbias, (const int*)pRT);
    mxt_kernel<<<512, 256>>>();

    for (int t = 0; t < NT; t++) {
        int par = t & 1;
        int npar = par ^ 1;
        gru_step<<<256, 256>>>(t, par, gbias);
        att_wa_step<<<32, 1024>>>(t, npar, v_att, memory);
    }

    // logits = attn_all @ Wo + bo : [2016,512] x [512,32000]
    sgemm128<<<dim3(VOCAB / 128, 16), 256>>>((const float*)pAll, Wo, out, BT, bo);
}

// round 12
// speedup vs baseline: 2.0780x; 1.0225x over previous
#include <cuda_runtime.h>
#include <cuda_bf16.h>
#include <math.h>
#include <stdint.h>

#define VOCAB 32000
#define EMB   256
#define UNITS 512
#define NB    32
#define NS    128
#define NT    63
#define N3U   1536
#define BT    (NB*NT)

__device__ float  g_MX [NT*NB*N3U];      // [t*32+b][1536] gemm output
__device__ float  g_MXT[NT*N3U*NB];      // [t][j][b] transposed
__device__ float  g_KEYS[NB*NS*UNITS];
__device__ float  g_WTK[N3U*UNITS];
__device__ float  g_WTR[N3U*UNITS];
__device__ float  g_WqT[UNITS*UNITS];
__device__ float  g_WaT[UNITS*2*UNITS];
__device__ float4 g_hQ  [2][128*32];     // [k4][b] packed 4 consecutive k
__device__ float4 g_attnQ[2][128*32];
__device__ float  g_attn_all[BT*UNITS];
__device__ int    g_rowtok[BT];
__device__ uint32_t g_WoHi[UNITS*VOCAB]; // tf32 hi of Wo
__device__ uint32_t g_WoLo[UNITS*VOCAB]; // tf32 lo of Wo

__device__ __forceinline__ float sigmoid_f(float x) {
    return 1.0f / (1.0f + __expf(-x));
}
__device__ __forceinline__ float tanh_fast(float x) {
    float y; asm("tanh.approx.f32 %0, %1;" : "=f"(y) : "f"(x)); return y;
}
__device__ __forceinline__ uint32_t f2tf32(float f) {
    uint32_t u; asm("cvt.rna.tf32.f32 %0, %1;" : "=r"(u) : "f"(f)); return u;
}
__device__ __forceinline__ void mma16n8k8(float* d, const uint32_t* a,
                                          uint32_t b0, uint32_t b1) {
    asm volatile("mma.sync.aligned.m16n8k8.row.col.f32.tf32.tf32.f32 "
        "{%0,%1,%2,%3}, {%4,%5,%6,%7}, {%8,%9}, {%0,%1,%2,%3};"
        : "+f"(d[0]), "+f"(d[1]), "+f"(d[2]), "+f"(d[3])
        : "r"(a[0]), "r"(a[1]), "r"(a[2]), "r"(a[3]), "r"(b0), "r"(b1));
}

// ------------------------- prep: transposes + init ---------------------------
__global__ void prep_kernel(const int* __restrict__ x, const float* __restrict__ enc,
                            const float* __restrict__ Kk, const float* __restrict__ Rk,
                            const float* __restrict__ Wq, const float* __restrict__ Wa)
{
    const int NWTK = N3U*UNITS, NWQ = UNITS*UNITS, NWA = UNITS*2*UNITS;
    const int total = NWTK + NWTK + NWQ + NWA + BT + NB*UNITS + NB*UNITS;
    for (int i = blockIdx.x*blockDim.x + threadIdx.x; i < total; i += gridDim.x*blockDim.x) {
        int j = i;
        if (j < NWTK) { int n = j >> 9, k = j & 511; g_WTK[j] = Kk[(EMB + k)*N3U + n]; continue; }
        j -= NWTK;
        if (j < NWTK) { int n = j >> 9, k = j & 511; g_WTR[j] = Rk[k*N3U + n]; continue; }
        j -= NWTK;
        if (j < NWQ)  { int u = j >> 9, k = j & 511; g_WqT[j] = Wq[k*UNITS + u]; continue; }
        j -= NWQ;
        if (j < NWA)  { int u = j >> 10, k = j & 1023; g_WaT[j] = Wa[k*UNITS + u]; continue; }
        j -= NWA;
        if (j < BT)   { int t = j >> 5, b = j & 31; g_rowtok[j] = x[b*NT + t]; continue; }
        j -= BT;
        if (j < NB*UNITS) {
            int b = j >> 9, u = j & 511;
            ((float*)g_hQ[0])[(((u >> 2) << 5) + b) * 4 + (u & 3)] = enc[j];
            continue;
        }
        j -= NB*UNITS;
        ((float*)g_attnQ[0])[j] = 0.0f;
    }
}

// ---------------- Wo split into tf32 hi/lo -----------------------------------
__global__ void split_wo(const float* __restrict__ Wo)
{
    const long total = (long)UNITS * VOCAB;
    for (long i = (long)blockIdx.x*blockDim.x + threadIdx.x; i < total;
         i += (long)gridDim.x*blockDim.x) {
        float f = Wo[i];
        uint32_t hi = f2tf32(f);
        float lo = f - __uint_as_float(hi);
        g_WoHi[i] = hi;
        g_WoLo[i] = f2tf32(lo);
    }
}

// ---------------- MX transpose: [t*32+b][1536] -> [t][j][b] ------------------
__global__ void mxt_kernel()
{
    const int total = NT*N3U*NB;
    for (int i = blockIdx.x*blockDim.x + threadIdx.x; i < total; i += gridDim.x*blockDim.x) {
        int b = i & 31;
        int j = (i >> 5) % N3U;
        int t = i / (N3U * NB);
        g_MXT[i] = g_MX[((long)(t * 32 + b)) * N3U + j];
    }
}

// ---------------- generic 64x64 tiled SGEMM, optional gather/bias ------------
__global__ void sgemm64(const float* __restrict__ A, int lda,
                        const float* __restrict__ B, int ldb,
                        float* __restrict__ C, int ldc,
                        int M, int N, int K,
                        const float* __restrict__ bias,
                        const int* __restrict__ gather)
{
    __shared__ float As[16][64];
    __shared__ float Bs[16][64];
    const int t = threadIdx.x;
    const int row0 = blockIdx.y << 6;
    const int col0 = blockIdx.x << 6;
    const int a_row = t >> 2, a_k = (t & 3) << 2;
    const int b_k = t >> 4, b_c = (t & 15) << 2;
    const int ty = t >> 4, tx = t & 15;

    float acc[4][4];
    #pragma unroll
    for (int i = 0; i < 4; i++)
        #pragma unroll
        for (int j = 0; j < 4; j++) acc[i][j] = 0.0f;

    const float* Ar = nullptr;
    {
        int ar = row0 + a_row;
        if (ar < M) {
            long r = gather ? (long)gather[ar] : (long)ar;
            Ar = A + r * (long)lda;
        }
    }

    for (int k0 = 0; k0 < K; k0 += 16) {
        float4 av = make_float4(0.f, 0.f, 0.f, 0.f);
        if (Ar) av = *(const float4*)(Ar + k0 + a_k);
        As[a_k + 0][a_row] = av.x;
        As[a_k + 1][a_row] = av.y;
        As[a_k + 2][a_row] = av.z;
        As[a_k + 3][a_row] = av.w;
        *(float4*)&Bs[b_k][b_c] = *(const float4*)(B + (long)(k0 + b_k) * ldb + col0 + b_c);
        __syncthreads();
        #pragma unroll
        for (int k = 0; k < 16; k++) {
            float4 a4 = *(const float4*)&As[k][ty << 2];
            float4 b4 = *(const float4*)&Bs[k][tx << 2];
            float a[4] = {a4.x, a4.y, a4.z, a4.w};
            float b[4] = {b4.x, b4.y, b4.z, b4.w};
            #pragma unroll
            for (int i = 0; i < 4; i++)
                #pragma unroll
                for (int j = 0; j < 4; j++)
                    acc[i][j] = fmaf(a[i], b[j], acc[i][j]);
        }
        __syncthreads();
    }

    #pragma unroll
    for (int i = 0; i < 4; i++) {
        int r = row0 + (ty << 2) + i;
        if (r < M) {
            int c = col0 + (tx << 2);
            float4 o;
            o.x = acc[i][0] + (bias ? bias[c + 0] : 0.f);
            o.y = acc[i][1] + (bias ? bias[c + 1] : 0.f);
            o.z = acc[i][2] + (bias ? bias[c + 2] : 0.f);
            o.w = acc[i][3] + (bias ? bias[c + 3] : 0.f);
            *(float4*)(C + (long)r * ldc + c) = o;
        }
    }
}

// ---------------- tf32 tensor-core logits GEMM (3xTF32) ----------------------
// C[M,VOCAB] = A[M,512] @ Wo[512,VOCAB] + bias.
// 128x128 CTA tile, 8 warps (2x4), warp tile 64x32 via mma.m16n8k8.
// grid = (row_tiles=16, col_tiles=250): row-fastest so B col-slices reuse L2.
__global__ __launch_bounds__(256) void tf32gemm(
    const float* __restrict__ A,
    const uint32_t* __restrict__ Bhi, const uint32_t* __restrict__ Blo,
    float* __restrict__ C, int M, const float* __restrict__ bias)
{
    __shared__ uint32_t AsHi[128][20], AsLo[128][20];
    __shared__ uint32_t BsHi[16][136], BsLo[16][136];
    const int t = threadIdx.x;
    const int w = t >> 5, lane = t & 31;
    const int wm = w >> 2, wn = w & 3;           // warp tile origin
    const int row0 = blockIdx.x << 7;
    const int col0 = blockIdx.y << 7;
    const int lr = lane >> 2, lc = lane & 3;

    float acc[4][4][4];
    #pragma unroll
    for (int mi = 0; mi < 4; mi++)
        #pragma unroll
        for (int ni = 0; ni < 4; ni++)
            #pragma unroll
            for (int q = 0; q < 4; q++) acc[mi][ni][q] = 0.0f;

    const int a_r = t >> 1, a_kq = (t & 1) << 3;   // A: 8 floats/thread
    const int b_k = t >> 4, b_nq = (t & 15) << 3;  // B: 8 u32/thread (hi & lo)
    const bool a_ok = (row0 + a_r) < M;
    const float* Ap = a_ok ? (A + (long)(row0 + a_r) * UNITS + a_kq) : nullptr;

    for (int k0 = 0; k0 < UNITS; k0 += 16) {
        float4 av0 = make_float4(0.f,0.f,0.f,0.f), av1 = av0;
        if (Ap) {
            av0 = *(const float4*)(Ap + k0);
            av1 = *(const float4*)(Ap + k0 + 4);
        }
        const uint32_t* bh = Bhi + (long)(k0 + b_k) * VOCAB + col0 + b_nq;
        const uint32_t* bl = Blo + (long)(k0 + b_k) * VOCAB + col0 + b_nq;
        uint4 bh0 = *(const uint4*)(bh), bh1 = *(const uint4*)(bh + 4);
        uint4 bl0 = *(const uint4*)(bl), bl1 = *(const uint4*)(bl + 4);
        __syncthreads();
        {
            float a[8] = {av0.x, av0.y, av0.z, av0.w, av1.x, av1.y, av1.z, av1.w};
            #pragma unroll
            for (int q = 0; q < 8; q++) {
                uint32_t hi = f2tf32(a[q]);
                AsHi[a_r][a_kq + q] = hi;
                AsLo[a_r][a_kq + q] = f2tf32(a[q] - __uint_as_float(hi));
            }
            *(uint4*)&BsHi[b_k][b_nq]     = bh0;
            *(uint4*)&BsHi[b_k][b_nq + 4] = bh1;
            *(uint4*)&BsLo[b_k][b_nq]     = bl0;
            *(uint4*)&BsLo[b_k][b_nq + 4] = bl1;
        }
        __syncthreads();

        #pragma unroll
        for (int kk = 0; kk < 2; kk++) {
            const int kb = kk << 3;
            uint32_t ahi[4][4], alo[4][4];
            #pragma unroll
            for (int mi = 0; mi < 4; mi++) {
                const int mr = (wm << 6) + (mi << 4) + lr;
                ahi[mi][0] = AsHi[mr][kb + lc];
                ahi[mi][1] = AsHi[mr + 8][kb + lc];
                ahi[mi][2] = AsHi[mr][kb + lc + 4];
                ahi[mi][3] = AsHi[mr + 8][kb + lc + 4];
                alo[mi][0] = AsLo[mr][kb + lc];
                alo[mi][1] = AsLo[mr + 8][kb + lc];
                alo[mi][2] = AsLo[mr][kb + lc + 4];
                alo[mi][3] = AsLo[mr + 8][kb + lc + 4];
            }
            #pragma unroll
            for (int ni = 0; ni < 4; ni++) {
                const int nc = (wn << 5) + (ni << 3) + lr;
                uint32_t bhi0 = BsHi[kb + lc][nc];
                uint32_t bhi1 = BsHi[kb + lc + 4][nc];
                uint32_t blo0 = BsLo[kb + lc][nc];
                uint32_t blo1 = BsLo[kb + lc + 4][nc];
                #pragma unroll
                for (int mi = 0; mi < 4; mi++) {
                    mma16n8k8(acc[mi][ni], ahi[mi], bhi0, bhi1);
                    mma16n8k8(acc[mi][ni], ahi[mi], blo0, blo1);
                    mma16n8k8(acc[mi][ni], alo[mi], bhi0, bhi1);
                }
            }
        }
    }

    // epilogue: c0/c1 at (row, 2lc), c2/c3 at (row+8, 2lc)
    #pragma unroll
    for (int mi = 0; mi < 4; mi++) {
        const int r = row0 + (wm << 6) + (mi << 4) + lr;
        #pragma unroll
        for (int ni = 0; ni < 4; ni++) {
            const int c = col0 + (wn << 5) + (ni << 3) + (lc << 1);
            float2 bv = *(const float2*)(bias + c);
            if (r < M) {
                float2 o = {acc[mi][ni][0] + bv.x, acc[mi][ni][1] + bv.y};
                *(float2*)(C + (long)r * VOCAB + c) = o;
            }
            if (r + 8 < M) {
                float2 o = {acc[mi][ni][2] + bv.x, acc[mi][ni][3] + bv.y};
                *(float2*)(C + (long)(r + 8) * VOCAB + c) = o;
            }
        }
    }
}

// ------------------------- per-step GRU gate kernel --------------------------
// 256 blocks x 256 threads. Warp = (ul 0..1, gf 0..1, kh 0..1); u = blk*2+ul.
__global__ __launch_bounds__(256) void gru_step(int t, int par,
                                                const float* __restrict__ gbias)
{
    __shared__ float red[8][3][32];
    const int tid = threadIdx.x, w = tid >> 5, lane = tid & 31;
    const int ul = w >> 2, gf = (w >> 1) & 1, kh = w & 1;
    const int u = (blockIdx.x << 1) + ul;

    const float4* __restrict__ act = (gf ? g_hQ[par] : g_attnQ[par]) + (kh << 11);
    const float* __restrict__ wb = gf ? g_WTR : g_WTK;
    const float* __restrict__ w0 = wb + ((long)u << 9) + (kh << 8);
    const float* __restrict__ w1 = w0 + (512 << 9);
    const float* __restrict__ w2 = w1 + (512 << 9);

    float az = 0.f, ar = 0.f, ah = 0.f;
    #pragma unroll 8
    for (int k4 = 0; k4 < 64; k4++) {
        float4 a  = act[(k4 << 5) + lane];
        float4 vz = *(const float4*)(w0 + (k4 << 2));
        float4 vr = *(const float4*)(w1 + (k4 << 2));
        float4 vh = *(const float4*)(w2 + (k4 << 2));
        az = fmaf(a.x, vz.x, az); ar = fmaf(a.x, vr.x, ar); ah = fmaf(a.x, vh.x, ah);
        az = fmaf(a.y, vz.y, az); ar = fmaf(a.y, vr.y, ar); ah = fmaf(a.y, vh.y, ah);
        az = fmaf(a.z, vz.z, az); ar = fmaf(a.z, vr.z, ar); ah = fmaf(a.z, vh.z, ah);
        az = fmaf(a.w, vz.w, az); ar = fmaf(a.w, vr.w, ar); ah = fmaf(a.w, vh.w, ah);
    }
    red[w][0][lane] = az;
    red[w][1][lane] = ar;
    red[w][2][lane] = ah;
    __syncthreads();

    if ((w & 3) == 0) {
        const int base = w;                  // 0 or 4
        float xz  = red[base + 0][0][lane] + red[base + 1][0][lane];
        float hz  = red[base + 2][0][lane] + red[base + 3][0][lane];
        float xr  = red[base + 0][1][lane] + red[base + 1][1][lane];
        float hr  = red[base + 2][1][lane] + red[base + 3][1][lane];
        float xh  = red[base + 0][2][lane] + red[base + 1][2][lane];
        float hhr = red[base + 2][2][lane] + red[base + 3][2][lane];

        const float* mx = g_MXT + (long)t * N3U * NB;
        float mz = mx[((u)        << 5) + lane];
        float mr = mx[((u + 512)  << 5) + lane];
        float mh = mx[((u + 1024) << 5) + lane];

        float z  = sigmoid_f(mz + xz + hz + gbias[N3U + u]);
        float r  = sigmoid_f(mr + xr + hr + gbias[N3U + 512 + u]);
        float hh = tanhf(mh + xh + r * (hhr + gbias[N3U + 1024 + u]));

        const float* hp = (const float*)g_hQ[par];
        float hold = hp[((((u >> 2) << 5) + lane) << 2) + (u & 3)];
        float hnew = z * hold + (1.0f - z) * hh;
        ((float*)g_hQ[par ^ 1])[((((u >> 2) << 5) + lane) << 2) + (u & 3)] = hnew;
    }
}

// -------- fused attention + Wa: 32 blocks (per batch) x 1024 threads ---------
__global__ __launch_bounds__(1024) void att_wa_step(
    int t, int npar, const float* __restrict__ v_att,
    const float* __restrict__ memory)
{
    __shared__ float hs[UNITS];
    __shared__ float pqs[UNITS];
    __shared__ float vsh[UNITS];
    __shared__ float ctxs[UNITS];
    __shared__ float sc[NS];
    const int b = blockIdx.x, tid = threadIdx.x;
    const int w = tid >> 5, lane = tid & 31;

    if (tid < UNITS) {
        const float* hp = (const float*)g_hQ[npar];
        hs[tid]  = hp[((((tid >> 2) << 5) + b) << 2) + (tid & 3)];
        vsh[tid] = v_att[tid];
    }
    __syncthreads();

    // pq[u] = h . WqT[u]    (32 warps x 16 u each)
    {
        #pragma unroll 1
        for (int uu = 0; uu < 16; uu++) {
            int u = (w << 4) + uu;
            const float* __restrict__ wr = g_WqT + ((long)u << 9);
            float acc = 0.f;
            #pragma unroll
            for (int j = 0; j < 4; j++) {
                float4 wv = *(const float4*)(wr + (j << 7) + (lane << 2));
                float4 hv = *(const float4*)(hs + (j << 7) + (lane << 2));
                acc = fmaf(hv.x, wv.x, acc);
                acc = fmaf(hv.y, wv.y, acc);
                acc = fmaf(hv.z, wv.z, acc);
                acc = fmaf(hv.w, wv.w, acc);
            }
            #pragma unroll
            for (int off = 16; off; off >>= 1) acc += __shfl_xor_sync(0xffffffffu, acc, off);
            if (lane == 0) pqs[u] = acc;
        }
    }
    __syncthreads();

    // scores[s] = v . tanh(keys[s] + pq)    (32 warps x 4 s each)
    {
        const float* __restrict__ keysb = g_KEYS + (long)b * NS * UNITS;
        #pragma unroll 1
        for (int si = 0; si < 4; si++) {
            int s = (w << 2) + si;
            const float* kr = keysb + (s << 9);
            float acc = 0.f;
            #pragma unroll
            for (int j = 0; j < 4; j++) {
                float4 kv = *(const float4*)(kr + (j << 7) + (lane << 2));
                float4 pv = *(const float4*)(pqs + (j << 7) + (lane << 2));
                float4 vv = *(const float4*)(vsh + (j << 7) + (lane << 2));
                acc = fmaf(vv.x, tanh_fast(kv.x + pv.x), acc);
                acc = fmaf(vv.y, tanh_fast(kv.y + pv.y), acc);
                acc = fmaf(vv.z, tanh_fast(kv.z + pv.z), acc);
                acc = fmaf(vv.w, tanh_fast(kv.w + pv.w), acc);
            }
            #pragma unroll
            for (int off = 16; off; off >>= 1) acc += __shfl_xor_sync(0xffffffffu, acc, off);
            if (lane == 0) sc[s] = acc;
        }
    }
    __syncthreads();

    // softmax over 128 scores: single warp
    if (tid < 32) {
        float s0 = sc[tid], s1 = sc[tid + 32], s2 = sc[tid + 64], s3 = sc[tid + 96];
        float m = fmaxf(fmaxf(s0, s1), fmaxf(s2, s3));
        #pragma unroll
        for (int off = 16; off; off >>= 1) m = fmaxf(m, __shfl_xor_sync(0xffffffffu, m, off));
        float e0 = __expf(s0 - m), e1 = __expf(s1 - m);
        float e2 = __expf(s2 - m), e3 = __expf(s3 - m);
        float ss = (e0 + e1) + (e2 + e3);
        #pragma unroll
        for (int off = 16; off; off >>= 1) ss += __shfl_xor_sync(0xffffffffu, ss, off);
        float inv = 1.0f / ss;
        sc[tid] = e0 * inv; sc[tid + 32] = e1 * inv;
        sc[tid + 64] = e2 * inv; sc[tid + 96] = e3 * inv;
    }
    __syncthreads();

    // context[u] = sum_s align[s] * memory[b][s][u]   (split s over 2 halves)
    {
        const float* __restrict__ memb = memory + (long)b * NS * UNITS;
        int u = tid & 511, sh = tid >> 9;
        float acc = 0.f;
        const float* mp = memb + ((sh << 6) << 9) + u;
        const float* scp = sc + (sh << 6);
        #pragma unroll 8
        for (int s = 0; s < 64; s++)
            acc = fmaf(scp[s], mp[s << 9], acc);
        if (sh == 0) ctxs[u] = acc;
        __syncthreads();
        if (sh == 1) ctxs[u] += acc;
    }
    __syncthreads();

    // attn_new[u] = [h | ctx] . WaT[u]   (32 warps x 16 u each)
    {
        float* aq = (float*)g_attnQ[npar];
        #pragma unroll 1
        for (int uu = 0; uu < 16; uu++) {
            int u = (w << 4) + uu;
            const float* __restrict__ wr = g_WaT + ((long)u << 10);
            float acc = 0.f;
            #pragma unroll
            for (int j = 0; j < 4; j++) {
                float4 wv = *(const float4*)(wr + (j << 7) + (lane << 2));
                float4 xv = *(const float4*)(hs + (j << 7) + (lane << 2));
                acc = fmaf(xv.x, wv.x, acc);
                acc = fmaf(xv.y, wv.y, acc);
                acc = fmaf(xv.z, wv.z, acc);
                acc = fmaf(xv.w, wv.w, acc);
            }
            #pragma unroll
            for (int j = 0; j < 4; j++) {
                float4 wv = *(const float4*)(wr + 512 + (j << 7) + (lane << 2));
                float4 xv = *(const float4*)(ctxs + (j << 7) + (lane << 2));
                acc = fmaf(xv.x, wv.x, acc);
                acc = fmaf(xv.y, wv.y, acc);
                acc = fmaf(xv.z, wv.z, acc);
                acc = fmaf(xv.w, wv.w, acc);
            }
            #pragma unroll
            for (int off = 16; off; off >>= 1) acc += __shfl_xor_sync(0xffffffffu, acc, off);
            if (lane == 0) {
                aq[((((u >> 2) << 5) + b) << 2) + (u & 3)] = acc;
                g_attn_all[((long)(b * NT + t) << 9) + u] = acc;
            }
        }
    }
}

extern "C" void kernel_launch(void* const* d_in, const int* in_sizes, int n_in,
                              void* d_out, int out_size) {
    const int*   x      = (const int*)d_in[0];
    const float* enc    = (const float*)d_in[1];
    const float* memory = (const float*)d_in[2];
    const float* E      = (const float*)d_in[3];
    const float* Kk     = (const float*)d_in[4];
    const float* Rk     = (const float*)d_in[5];
    const float* gbias  = (const float*)d_in[6];
    const float* Wq     = (const float*)d_in[7];
    const float* Wk     = (const float*)d_in[8];
    const float* v_att  = (const float*)d_in[9];
    const float* Wa     = (const float*)d_in[10];
    const float* Wo     = (const float*)d_in[11];
    const float* bo     = (const float*)d_in[12];
    float* out = (float*)d_out;

    void *pKEYS, *pMX, *pAll, *pRT, *pWoHi, *pWoLo;
    cudaGetSymbolAddress(&pKEYS, g_KEYS);
    cudaGetSymbolAddress(&pMX,   g_MX);
    cudaGetSymbolAddress(&pAll,  g_attn_all);
    cudaGetSymbolAddress(&pRT,   g_rowtok);
    cudaGetSymbolAddress(&pWoHi, g_WoHi);
    cudaGetSymbolAddress(&pWoLo, g_WoLo);

    prep_kernel<<<256, 256>>>(x, enc, Kk, Rk, Wq, Wa);
    split_wo<<<1024, 256>>>(Wo);

    // keys = memory @ Wk : [4096,512] x [512,512]
    sgemm64<<<dim3(8, 64), 256>>>(memory, UNITS, Wk, UNITS,
                                  (float*)pKEYS, UNITS, NB*NS, UNITS, UNITS,
                                  nullptr, nullptr);
    // MX = E[rowtok] @ K_kernel[:256,:] + bias0 : [2016,256] x [256,1536]
    sgemm64<<<dim3(24, 32), 256>>>(E, EMB, Kk, N3U,
                                   (float*)pMX, N3U, BT, N3U, EMB,
                                   gbias, (const int*)pRT);
    mxt_kernel<<<512, 256>>>();

    for (int t = 0; t < NT; t++) {
        int par = t & 1;
        int npar = par ^ 1;
        gru_step<<<256, 256>>>(t, par, gbias);
        att_wa_step<<<32, 1024>>>(t, npar, v_att, memory);
    }

    // logits = attn_all @ Wo + bo : [2016,512] x [512,32000]  (3xTF32 tensor)
    tf32gemm<<<dim3(16, VOCAB / 128), 256>>>((const float*)pAll,
                                             (const uint32_t*)pWoHi,
                                             (const uint32_t*)pWoLo,
                                             out, BT, bo);
}

// round 13
// speedup vs baseline: 2.5680x; 1.2358x over previous
#include <cuda_runtime.h>
#include <cuda_bf16.h>
#include <math.h>
#include <stdint.h>

#define VOCAB 32000
#define EMB   256
#define UNITS 512
#define NB    32
#define NS    128
#define NT    63
#define N3U   1536
#define BT    (NB*NT)
#define K2    256          // UNITS/2 packed bf16 pairs
#define MROWS 2048         // BT padded to 128

__device__ float  g_MX [NT*NB*N3U];      // [t*32+b][1536] gemm output
__device__ float  g_MXT[NT*N3U*NB];      // [t][j][b] transposed
__device__ float  g_KEYS[NB*NS*UNITS];
__device__ float  g_WTK[N3U*UNITS];
__device__ float  g_WTR[N3U*UNITS];
__device__ float  g_WqT[UNITS*UNITS];
__device__ float  g_WaT[UNITS*2*UNITS];
__device__ float4 g_hQ  [2][128*32];     // [k4][b] packed 4 consecutive k
__device__ float4 g_attnQ[2][128*32];
__device__ float  g_attn_all[BT*UNITS];
__device__ int    g_rowtok[BT];
__device__ uint32_t g_WoHiP[K2*VOCAB];   // bf16 pair-packed Wo hi
__device__ uint32_t g_WoLoP[K2*VOCAB];   // bf16 pair-packed Wo lo
__device__ uint32_t g_AHiP[K2*MROWS];    // bf16 pair-packed attn_all hi [k2][row]
__device__ uint32_t g_ALoP[K2*MROWS];

__device__ __forceinline__ float sigmoid_f(float x) {
    return 1.0f / (1.0f + __expf(-x));
}
__device__ __forceinline__ float tanh_fast(float x) {
    float y; asm("tanh.approx.f32 %0, %1;" : "=f"(y) : "f"(x)); return y;
}
__device__ __forceinline__ void split_pack(float f0, float f1,
                                           uint32_t& hi, uint32_t& lo) {
    __nv_bfloat16 h0 = __float2bfloat16_rn(f0);
    __nv_bfloat16 h1 = __float2bfloat16_rn(f1);
    __nv_bfloat16 l0 = __float2bfloat16_rn(f0 - __bfloat162float(h0));
    __nv_bfloat16 l1 = __float2bfloat16_rn(f1 - __bfloat162float(h1));
    hi = (uint32_t)*(uint16_t*)&h0 | ((uint32_t)*(uint16_t*)&h1 << 16);
    lo = (uint32_t)*(uint16_t*)&l0 | ((uint32_t)*(uint16_t*)&l1 << 16);
}
__device__ __forceinline__ void mma_bf16(float* d, const uint32_t* a,
                                         uint32_t b0, uint32_t b1) {
    asm volatile("mma.sync.aligned.m16n8k16.row.col.f32.bf16.bf16.f32 "
        "{%0,%1,%2,%3}, {%4,%5,%6,%7}, {%8,%9}, {%0,%1,%2,%3};"
        : "+f"(d[0]), "+f"(d[1]), "+f"(d[2]), "+f"(d[3])
        : "r"(a[0]), "r"(a[1]), "r"(a[2]), "r"(a[3]), "r"(b0), "r"(b1));
}

// ------------------------- prep: transposes + init ---------------------------
__global__ void prep_kernel(const int* __restrict__ x, const float* __restrict__ enc,
                            const float* __restrict__ Kk, const float* __restrict__ Rk,
                            const float* __restrict__ Wq, const float* __restrict__ Wa)
{
    const int NWTK = N3U*UNITS, NWQ = UNITS*UNITS, NWA = UNITS*2*UNITS;
    const int total = NWTK + NWTK + NWQ + NWA + BT + NB*UNITS + NB*UNITS;
    for (int i = blockIdx.x*blockDim.x + threadIdx.x; i < total; i += gridDim.x*blockDim.x) {
        int j = i;
        if (j < NWTK) { int n = j >> 9, k = j & 511; g_WTK[j] = Kk[(EMB + k)*N3U + n]; continue; }
        j -= NWTK;
        if (j < NWTK) { int n = j >> 9, k = j & 511; g_WTR[j] = Rk[k*N3U + n]; continue; }
        j -= NWTK;
        if (j < NWQ)  { int u = j >> 9, k = j & 511; g_WqT[j] = Wq[k*UNITS + u]; continue; }
        j -= NWQ;
        if (j < NWA)  { int u = j >> 10, k = j & 1023; g_WaT[j] = Wa[k*UNITS + u]; continue; }
        j -= NWA;
        if (j < BT)   { int t = j >> 5, b = j & 31; g_rowtok[j] = x[b*NT + t]; continue; }
        j -= BT;
        if (j < NB*UNITS) {
            int b = j >> 9, u = j & 511;
            ((float*)g_hQ[0])[(((u >> 2) << 5) + b) * 4 + (u & 3)] = enc[j];
            continue;
        }
        j -= NB*UNITS;
        ((float*)g_attnQ[0])[j] = 0.0f;
    }
}

// ---------------- Wo split into pair-packed bf16 hi/lo -----------------------
// grid (125, 256): y = k2, x*256+tid = n
__global__ void split_wo(const float* __restrict__ Wo)
{
    const int k2 = blockIdx.y;
    const int n = blockIdx.x * 256 + threadIdx.x;
    float f0 = Wo[(long)(2*k2)     * VOCAB + n];
    float f1 = Wo[(long)(2*k2 + 1) * VOCAB + n];
    uint32_t hi, lo;
    split_pack(f0, f1, hi, lo);
    g_WoHiP[(long)k2 * VOCAB + n] = hi;
    g_WoLoP[(long)k2 * VOCAB + n] = lo;
}

// ---------------- attn_all split into pair-packed bf16 hi/lo -----------------
__global__ void asplit()
{
    const int total = K2 * MROWS;
    for (int i = blockIdx.x*blockDim.x + threadIdx.x; i < total; i += gridDim.x*blockDim.x) {
        int row = i >> 8, k2 = i & 255;
        uint32_t hi = 0, lo = 0;
        if (row < BT) {
            float2 f = *(const float2*)(g_attn_all + (long)row * UNITS + (k2 << 1));
            split_pack(f.x, f.y, hi, lo);
        }
        g_AHiP[k2 * MROWS + row] = hi;
        g_ALoP[k2 * MROWS + row] = lo;
    }
}

// ---------------- MX transpose: [t*32+b][1536] -> [t][j][b] ------------------
__global__ void mxt_kernel()
{
    const int total = NT*N3U*NB;
    for (int i = blockIdx.x*blockDim.x + threadIdx.x; i < total; i += gridDim.x*blockDim.x) {
        int b = i & 31;
        int j = (i >> 5) % N3U;
        int t = i / (N3U * NB);
        g_MXT[i] = g_MX[((long)(t * 32 + b)) * N3U + j];
    }
}

// ---------------- generic 64x64 tiled SGEMM, optional gather/bias ------------
__global__ void sgemm64(const float* __restrict__ A, int lda,
                        const float* __restrict__ B, int ldb,
                        float* __restrict__ C, int ldc,
                        int M, int N, int K,
                        const float* __restrict__ bias,
                        const int* __restrict__ gather)
{
    __shared__ float As[16][64];
    __shared__ float Bs[16][64];
    const int t = threadIdx.x;
    const int row0 = blockIdx.y << 6;
    const int col0 = blockIdx.x << 6;
    const int a_row = t >> 2, a_k = (t & 3) << 2;
    const int b_k = t >> 4, b_c = (t & 15) << 2;
    const int ty = t >> 4, tx = t & 15;

    float acc[4][4];
    #pragma unroll
    for (int i = 0; i < 4; i++)
        #pragma unroll
        for (int j = 0; j < 4; j++) acc[i][j] = 0.0f;

    const float* Ar = nullptr;
    {
        int ar = row0 + a_row;
        if (ar < M) {
            long r = gather ? (long)gather[ar] : (long)ar;
            Ar = A + r * (long)lda;
        }
    }

    for (int k0 = 0; k0 < K; k0 += 16) {
        float4 av = make_float4(0.f, 0.f, 0.f, 0.f);
        if (Ar) av = *(const float4*)(Ar + k0 + a_k);
        As[a_k + 0][a_row] = av.x;
        As[a_k + 1][a_row] = av.y;
        As[a_k + 2][a_row] = av.z;
        As[a_k + 3][a_row] = av.w;
        *(float4*)&Bs[b_k][b_c] = *(const float4*)(B + (long)(k0 + b_k) * ldb + col0 + b_c);
        __syncthreads();
        #pragma unroll
        for (int k = 0; k < 16; k++) {
            float4 a4 = *(const float4*)&As[k][ty << 2];
            float4 b4 = *(const float4*)&Bs[k][tx << 2];
            float a[4] = {a4.x, a4.y, a4.z, a4.w};
            float b[4] = {b4.x, b4.y, b4.z, b4.w};
            #pragma unroll
            for (int i = 0; i < 4; i++)
                #pragma unroll
                for (int j = 0; j < 4; j++)
                    acc[i][j] = fmaf(a[i], b[j], acc[i][j]);
        }
        __syncthreads();
    }

    #pragma unroll
    for (int i = 0; i < 4; i++) {
        int r = row0 + (ty << 2) + i;
        if (r < M) {
            int c = col0 + (tx << 2);
            float4 o;
            o.x = acc[i][0] + (bias ? bias[c + 0] : 0.f);
            o.y = acc[i][1] + (bias ? bias[c + 1] : 0.f);
            o.z = acc[i][2] + (bias ? bias[c + 2] : 0.f);
            o.w = acc[i][3] + (bias ? bias[c + 3] : 0.f);
            *(float4*)(C + (long)r * ldc + c) = o;
        }
    }
}

// ---------------- bf16 split tensor-core logits GEMM -------------------------
// C = A @ Wo + bias via hi*hi + hi*lo + lo*hi (bf16 2-term split, fp32 accum).
// 128x128 CTA tile, 8 warps (2x4), warp tile 64x32 via mma.m16n8k16.
// grid = (16 row tiles, 250 col tiles), row-fastest for B L2 reuse.
__global__ __launch_bounds__(256) void bf16gemm(
    const uint32_t* __restrict__ Ahi, const uint32_t* __restrict__ Alo,
    const uint32_t* __restrict__ Bhi, const uint32_t* __restrict__ Blo,
    float* __restrict__ C, int M, const float* __restrict__ bias)
{
    __shared__ uint32_t AsHi[8][136], AsLo[8][136];   // [k2][row]
    __shared__ uint32_t BsHi[8][136], BsLo[8][136];   // [k2][n]
    const int t = threadIdx.x;
    const int w = t >> 5, lane = t & 31;
    const int wm = w >> 2, wn = w & 3;
    const int row0 = blockIdx.x << 7;
    const int col0 = blockIdx.y << 7;
    const int lr = lane >> 2, lc = lane & 3;

    float acc[4][4][4];
    #pragma unroll
    for (int mi = 0; mi < 4; mi++)
        #pragma unroll
        for (int ni = 0; ni < 4; ni++)
            #pragma unroll
            for (int q = 0; q < 4; q++) acc[mi][ni][q] = 0.0f;

    const int s_k2 = t >> 5, s_q = (t & 31) << 2;   // staging: warp=k2 row, lane*4
    const uint32_t* ApH = Ahi + (long)s_k2 * MROWS + row0 + s_q;
    const uint32_t* ApL = Alo + (long)s_k2 * MROWS + row0 + s_q;
    const uint32_t* BpH = Bhi + (long)s_k2 * VOCAB + col0 + s_q;
    const uint32_t* BpL = Blo + (long)s_k2 * VOCAB + col0 + s_q;

    for (int c8 = 0; c8 < K2 / 8; c8++) {
        uint4 ah4 = *(const uint4*)(ApH + (long)(c8 * 8) * MROWS);
        uint4 al4 = *(const uint4*)(ApL + (long)(c8 * 8) * MROWS);
        uint4 bh4 = *(const uint4*)(BpH + (long)(c8 * 8) * VOCAB);
        uint4 bl4 = *(const uint4*)(BpL + (long)(c8 * 8) * VOCAB);
        __syncthreads();
        *(uint4*)&AsHi[s_k2][s_q] = ah4;
        *(uint4*)&AsLo[s_k2][s_q] = al4;
        *(uint4*)&BsHi[s_k2][s_q] = bh4;
        *(uint4*)&BsLo[s_k2][s_q] = bl4;
        __syncthreads();

        uint32_t ah[4][4], al[4][4];
        #pragma unroll
        for (int mi = 0; mi < 4; mi++) {
            const int r = (wm << 6) + (mi << 4) + lr;
            ah[mi][0] = AsHi[lc][r];     ah[mi][1] = AsHi[lc][r + 8];
            ah[mi][2] = AsHi[lc + 4][r]; ah[mi][3] = AsHi[lc + 4][r + 8];
            al[mi][0] = AsLo[lc][r];     al[mi][1] = AsLo[lc][r + 8];
            al[mi][2] = AsLo[lc + 4][r]; al[mi][3] = AsLo[lc + 4][r + 8];
        }
        #pragma unroll
        for (int ni = 0; ni < 4; ni++) {
            const int n = (wn << 5) + (ni << 3) + lr;
            uint32_t bh0 = BsHi[lc][n], bh1 = BsHi[lc + 4][n];
            uint32_t bl0 = BsLo[lc][n], bl1 = BsLo[lc + 4][n];
            #pragma unroll
            for (int mi = 0; mi < 4; mi++) {
                mma_bf16(acc[mi][ni], ah[mi], bh0, bh1);
                mma_bf16(acc[mi][ni], ah[mi], bl0, bl1);
                mma_bf16(acc[mi][ni], al[mi], bh0, bh1);
            }
        }
    }

    #pragma unroll
    for (int mi = 0; mi < 4; mi++) {
        const int r = row0 + (wm << 6) + (mi << 4) + lr;
        #pragma unroll
        for (int ni = 0; ni < 4; ni++) {
            const int c = col0 + (wn << 5) + (ni << 3) + (lc << 1);
            float2 bv = *(const float2*)(bias + c);
            if (r < M) {
                float2 o = {acc[mi][ni][0] + bv.x, acc[mi][ni][1] + bv.y};
                *(float2*)(C + (long)r * VOCAB + c) = o;
            }
            if (r + 8 < M) {
                float2 o = {acc[mi][ni][2] + bv.x, acc[mi][ni][3] + bv.y};
                *(float2*)(C + (long)(r + 8) * VOCAB + c) = o;
            }
        }
    }
}

// ------------------------- per-step GRU gate kernel --------------------------
// 256 blocks x 256 threads. Warp = (ul 0..1, gf 0..1, kh 0..1); u = blk*2+ul.
__global__ __launch_bounds__(256) void gru_step(int t, int par,
                                                const float* __restrict__ gbias)
{
    __shared__ float red[8][3][32];
    const int tid = threadIdx.x, w = tid >> 5, lane = tid & 31;
    const int ul = w >> 2, gf = (w >> 1) & 1, kh = w & 1;
    const int u = (blockIdx.x << 1) + ul;

    const float4* __restrict__ act = (gf ? g_hQ[par] : g_attnQ[par]) + (kh << 11);
    const float* __restrict__ wb = gf ? g_WTR : g_WTK;
    const float* __restrict__ w0 = wb + ((long)u << 9) + (kh << 8);
    const float* __restrict__ w1 = w0 + (512 << 9);
    const float* __restrict__ w2 = w1 + (512 << 9);

    float az = 0.f, ar = 0.f, ah = 0.f;
    #pragma unroll 8
    for (int k4 = 0; k4 < 64; k4++) {
        float4 a  = act[(k4 << 5) + lane];
        float4 vz = *(const float4*)(w0 + (k4 << 2));
        float4 vr = *(const float4*)(w1 + (k4 << 2));
        float4 vh = *(const float4*)(w2 + (k4 << 2));
        az = fmaf(a.x, vz.x, az); ar = fmaf(a.x, vr.x, ar); ah = fmaf(a.x, vh.x, ah);
        az = fmaf(a.y, vz.y, az); ar = fmaf(a.y, vr.y, ar); ah = fmaf(a.y, vh.y, ah);
        az = fmaf(a.z, vz.z, az); ar = fmaf(a.z, vr.z, ar); ah = fmaf(a.z, vh.z, ah);
        az = fmaf(a.w, vz.w, az); ar = fmaf(a.w, vr.w, ar); ah = fmaf(a.w, vh.w, ah);
    }
    red[w][0][lane] = az;
    red[w][1][lane] = ar;
    red[w][2][lane] = ah;
    __syncthreads();

    if ((w & 3) == 0) {
        const int base = w;                  // 0 or 4
        float xz  = red[base + 0][0][lane] + red[base + 1][0][lane];
        float hz  = red[base + 2][0][lane] + red[base + 3][0][lane];
        float xr  = red[base + 0][1][lane] + red[base + 1][1][lane];
        float hr  = red[base + 2][1][lane] + red[base + 3][1][lane];
        float xh  = red[base + 0][2][lane] + red[base + 1][2][lane];
        float hhr = red[base + 2][2][lane] + red[base + 3][2][lane];

        const float* mx = g_MXT + (long)t * N3U * NB;
        float mz = mx[((u)        << 5) + lane];
        float mr = mx[((u + 512)  << 5) + lane];
        float mh = mx[((u + 1024) << 5) + lane];

        float z  = sigmoid_f(mz + xz + hz + gbias[N3U + u]);
        float r  = sigmoid_f(mr + xr + hr + gbias[N3U + 512 + u]);
        float hh = tanhf(mh + xh + r * (hhr + gbias[N3U + 1024 + u]));

        const float* hp = (const float*)g_hQ[par];
        float hold = hp[((((u >> 2) << 5) + lane) << 2) + (u & 3)];
        float hnew = z * hold + (1.0f - z) * hh;
        ((float*)g_hQ[par ^ 1])[((((u >> 2) << 5) + lane) << 2) + (u & 3)] = hnew;
    }
}

// -------- fused attention + Wa: 32 blocks (per batch) x 1024 threads ---------
__global__ __launch_bounds__(1024) void att_wa_step(
    int t, int npar, const float* __restrict__ v_att,
    const float* __restrict__ memory)
{
    __shared__ float hs[UNITS];
    __shared__ float pqs[UNITS];
    __shared__ float vsh[UNITS];
    __shared__ float ctxs[UNITS];
    __shared__ float sc[NS];
    const int b = blockIdx.x, tid = threadIdx.x;
    const int w = tid >> 5, lane = tid & 31;

    if (tid < UNITS) {
        const float* hp = (const float*)g_hQ[npar];
        hs[tid]  = hp[((((tid >> 2) << 5) + b) << 2) + (tid & 3)];
        vsh[tid] = v_att[tid];
    }
    __syncthreads();

    // pq[u] = h . WqT[u]    (32 warps x 16 u each)
    {
        #pragma unroll 1
        for (int uu = 0; uu < 16; uu++) {
            int u = (w << 4) + uu;
            const float* __restrict__ wr = g_WqT + ((long)u << 9);
            float acc = 0.f;
            #pragma unroll
            for (int j = 0; j < 4; j++) {
                float4 wv = *(const float4*)(wr + (j << 7) + (lane << 2));
                float4 hv = *(const float4*)(hs + (j << 7) + (lane << 2));
                acc = fmaf(hv.x, wv.x, acc);
                acc = fmaf(hv.y, wv.y, acc);
                acc = fmaf(hv.z, wv.z, acc);
                acc = fmaf(hv.w, wv.w, acc);
            }
            #pragma unroll
            for (int off = 16; off; off >>= 1) acc += __shfl_xor_sync(0xffffffffu, acc, off);
            if (lane == 0) pqs[u] = acc;
        }
    }
    __syncthreads();

    // scores[s] = v . tanh(keys[s] + pq)    (32 warps x 4 s each)
    {
        const float* __restrict__ keysb = g_KEYS + (long)b * NS * UNITS;
        #pragma unroll 1
        for (int si = 0; si < 4; si++) {
            int s = (w << 2) + si;
            const float* kr = keysb + (s << 9);
            float acc = 0.f;
            #pragma unroll
            for (int j = 0; j < 4; j++) {
                float4 kv = *(const float4*)(kr + (j << 7) + (lane << 2));
                float4 pv = *(const float4*)(pqs + (j << 7) + (lane << 2));
                float4 vv = *(const float4*)(vsh + (j << 7) + (lane << 2));
                acc = fmaf(vv.x, tanh_fast(kv.x + pv.x), acc);
                acc = fmaf(vv.y, tanh_fast(kv.y + pv.y), acc);
                acc = fmaf(vv.z, tanh_fast(kv.z + pv.z), acc);
                acc = fmaf(vv.w, tanh_fast(kv.w + pv.w), acc);
            }
            #pragma unroll
            for (int off = 16; off; off >>= 1) acc += __shfl_xor_sync(0xffffffffu, acc, off);
            if (lane == 0) sc[s] = acc;
        }
    }
    __syncthreads();

    // softmax over 128 scores: single warp
    if (tid < 32) {
        float s0 = sc[tid], s1 = sc[tid + 32], s2 = sc[tid + 64], s3 = sc[tid + 96];
        float m = fmaxf(fmaxf(s0, s1), fmaxf(s2, s3));
        #pragma unroll
        for (int off = 16; off; off >>= 1) m = fmaxf(m, __shfl_xor_sync(0xffffffffu, m, off));
        float e0 = __expf(s0 - m), e1 = __expf(s1 - m);
        float e2 = __expf(s2 - m), e3 = __expf(s3 - m);
        float ss = (e0 + e1) + (e2 + e3);
        #pragma unroll
        for (int off = 16; off; off >>= 1) ss += __shfl_xor_sync(0xffffffffu, ss, off);
        float inv = 1.0f / ss;
        sc[tid] = e0 * inv; sc[tid + 32] = e1 * inv;
        sc[tid + 64] = e2 * inv; sc[tid + 96] = e3 * inv;
    }
    __syncthreads();

    // context[u] = sum_s align[s] * memory[b][s][u]   (split s over 2 halves)
    {
        const float* __restrict__ memb = memory + (long)b * NS * UNITS;
        int u = tid & 511, sh = tid >> 9;
        float acc = 0.f;
        const float* mp = memb + ((sh << 6) << 9) + u;
        const float* scp = sc + (sh << 6);
        #pragma unroll 8
        for (int s = 0; s < 64; s++)
            acc = fmaf(scp[s], mp[s << 9], acc);
        if (sh == 0) ctxs[u] = acc;
        __syncthreads();
        if (sh == 1) ctxs[u] += acc;
    }
    __syncthreads();

    // attn_new[u] = [h | ctx] . WaT[u]   (32 warps x 16 u each)
    {
        float* aq = (float*)g_attnQ[npar];
        #pragma unroll 1
        for (int uu = 0; uu < 16; uu++) {
            int u = (w << 4) + uu;
            const float* __restrict__ wr = g_WaT + ((long)u << 10);
            float acc = 0.f;
            #pragma unroll
            for (int j = 0; j < 4; j++) {
                float4 wv = *(const float4*)(wr + (j << 7) + (lane << 2));
                float4 xv = *(const float4*)(hs + (j << 7) + (lane << 2));
                acc = fmaf(xv.x, wv.x, acc);
                acc = fmaf(xv.y, wv.y, acc);
                acc = fmaf(xv.z, wv.z, acc);
                acc = fmaf(xv.w, wv.w, acc);
            }
            #pragma unroll
            for (int j = 0; j < 4; j++) {
                float4 wv = *(const float4*)(wr + 512 + (j << 7) + (lane << 2));
                float4 xv = *(const float4*)(ctxs + (j << 7) + (lane << 2));
                acc = fmaf(xv.x, wv.x, acc);
                acc = fmaf(xv.y, wv.y, acc);
                acc = fmaf(xv.z, wv.z, acc);
                acc = fmaf(xv.w, wv.w, acc);
            }
            #pragma unroll
            for (int off = 16; off; off >>= 1) acc += __shfl_xor_sync(0xffffffffu, acc, off);
            if (lane == 0) {
                aq[((((u >> 2) << 5) + b) << 2) + (u & 3)] = acc;
                g_attn_all[((long)(b * NT + t) << 9) + u] = acc;
            }
        }
    }
}

extern "C" void kernel_launch(void* const* d_in, const int* in_sizes, int n_in,
                              void* d_out, int out_size) {
    const int*   x      = (const int*)d_in[0];
    const float* enc    = (const float*)d_in[1];
    const float* memory = (const float*)d_in[2];
    const float* E      = (const float*)d_in[3];
    const float* Kk     = (const float*)d_in[4];
    const float* Rk     = (const float*)d_in[5];
    const float* gbias  = (const float*)d_in[6];
    const float* Wq     = (const float*)d_in[7];
    const float* Wk     = (const float*)d_in[8];
    const float* v_att  = (const float*)d_in[9];
    const float* Wa     = (const float*)d_in[10];
    const float* Wo     = (const float*)d_in[11];
    const float* bo     = (const float*)d_in[12];
    float* out = (float*)d_out;

    void *pKEYS, *pMX, *pRT, *pWoHi, *pWoLo, *pAHi, *pALo;
    cudaGetSymbolAddress(&pKEYS, g_KEYS);
    cudaGetSymbolAddress(&pMX,   g_MX);
    cudaGetSymbolAddress(&pRT,   g_rowtok);
    cudaGetSymbolAddress(&pWoHi, g_WoHiP);
    cudaGetSymbolAddress(&pWoLo, g_WoLoP);
    cudaGetSymbolAddress(&pAHi,  g_AHiP);
    cudaGetSymbolAddress(&pALo,  g_ALoP);

    prep_kernel<<<256, 256>>>(x, enc, Kk, Rk, Wq, Wa);
    split_wo<<<dim3(125, 256), 256>>>(Wo);

    // keys = memory @ Wk : [4096,512] x [512,512]
    sgemm64<<<dim3(8, 64), 256>>>(memory, UNITS, Wk, UNITS,
                                  (float*)pKEYS, UNITS, NB*NS, UNITS, UNITS,
                                  nullptr, nullptr);
    // MX = E[rowtok] @ K_kernel[:256,:] + bias0 : [2016,256] x [256,1536]
    sgemm64<<<dim3(24, 32), 256>>>(E, EMB, Kk, N3U,
                                   (float*)pMX, N3U, BT, N3U, EMB,
                                   gbias, (const int*)pRT);
    mxt_kernel<<<512, 256>>>();

    for (int t = 0; t < NT; t++) {
        int par = t & 1;
        int npar = par ^ 1;
        gru_step<<<256, 256>>>(t, par, gbias);
        att_wa_step<<<32, 1024>>>(t, npar, v_att, memory);
    }

    // pack attn_all into bf16 hi/lo, then logits = attn_all @ Wo + bo
    asplit<<<512, 256>>>();
    bf16gemm<<<dim3(16, VOCAB / 128), 256>>>((const uint32_t*)pAHi,
                                             (const uint32_t*)pALo,
                                             (const uint32_t*)pWoHi,
                                             (const uint32_t*)pWoLo,
                                             out, BT, bo);
}

// round 14
// speedup vs baseline: 2.6809x; 1.0440x over previous
#include <cuda_runtime.h>
#include <cuda_bf16.h>
#include <math.h>
#include <stdint.h>

#define VOCAB 32000
#define EMB   256
#define UNITS 512
#define NB    32
#define NS    128
#define NT    63
#define N3U   1536
#define BT    (NB*NT)
#define K2    256          // UNITS/2 packed bf16 pairs
#define MROWS 2048         // BT padded to 128
#define RGRID 128          // persistent recurrence grid (< 148 SMs)

__device__ float  g_MX [NT*NB*N3U];      // [t*32+b][1536] gemm output
__device__ float  g_MXT[NT*N3U*NB];      // [t][j][b] transposed
__device__ float  g_KEYS[NB*NS*UNITS];
__device__ float  g_WTK[N3U*UNITS];
__device__ float  g_WTR[N3U*UNITS];
__device__ float  g_WqT[UNITS*UNITS];
__device__ float  g_WaT[UNITS*2*UNITS];
__device__ float4 g_hQ  [2][128*32];     // [k4][b] packed 4 consecutive k
__device__ float4 g_attnQ[2][128*32];
__device__ float  g_attn_all[BT*UNITS];
__device__ int    g_rowtok[BT];
__device__ uint32_t g_WoHiP[K2*VOCAB];   // bf16 pair-packed Wo hi
__device__ uint32_t g_WoLoP[K2*VOCAB];   // bf16 pair-packed Wo lo
__device__ uint32_t g_AHiP[K2*MROWS];    // bf16 pair-packed attn_all hi [k2][row]
__device__ uint32_t g_ALoP[K2*MROWS];
__device__ unsigned g_bar_count;
__device__ unsigned g_bar_gen;

__device__ __forceinline__ float sigmoid_f(float x) {
    return 1.0f / (1.0f + __expf(-x));
}
__device__ __forceinline__ float tanh_fast(float x) {
    float y; asm("tanh.approx.f32 %0, %1;" : "=f"(y) : "f"(x)); return y;
}
__device__ __forceinline__ void split_pack(float f0, float f1,
                                           uint32_t& hi, uint32_t& lo) {
    __nv_bfloat16 h0 = __float2bfloat16_rn(f0);
    __nv_bfloat16 h1 = __float2bfloat16_rn(f1);
    __nv_bfloat16 l0 = __float2bfloat16_rn(f0 - __bfloat162float(h0));
    __nv_bfloat16 l1 = __float2bfloat16_rn(f1 - __bfloat162float(h1));
    hi = (uint32_t)*(uint16_t*)&h0 | ((uint32_t)*(uint16_t*)&h1 << 16);
    lo = (uint32_t)*(uint16_t*)&l0 | ((uint32_t)*(uint16_t*)&l1 << 16);
}
__device__ __forceinline__ void mma_bf16(float* d, const uint32_t* a,
                                         uint32_t b0, uint32_t b1) {
    asm volatile("mma.sync.aligned.m16n8k16.row.col.f32.bf16.bf16.f32 "
        "{%0,%1,%2,%3}, {%4,%5,%6,%7}, {%8,%9}, {%0,%1,%2,%3};"
        : "+f"(d[0]), "+f"(d[1]), "+f"(d[2]), "+f"(d[3])
        : "r"(a[0]), "r"(a[1]), "r"(a[2]), "r"(a[3]), "r"(b0), "r"(b1));
}

// Grid-wide barrier for the persistent recurrence kernel. Safe because
// RGRID (128) <= SM count (148) with 1024-thread blocks -> wave-1 co-residency.
// Release fence is cumulative (pushes CTA-bar-observed writes to GPU scope);
// the trailing __threadfence() emits CCTL.IVALL -> invalidates stale L1D.
__device__ __forceinline__ void grid_barrier(unsigned& gen)
{
    __syncthreads();
    if (threadIdx.x == 0) {
        __threadfence();
        if (atomicAdd(&g_bar_count, 1u) == RGRID - 1) {
            g_bar_count = 0u;
            __threadfence();
            atomicExch(&g_bar_gen, gen + 1u);
        } else {
            while (atomicAdd(&g_bar_gen, 0u) <= gen) __nanosleep(64);
        }
        __threadfence();
    }
    __syncthreads();
    gen++;
}

// ------------------------- prep: transposes + init ---------------------------
__global__ void prep_kernel(const int* __restrict__ x, const float* __restrict__ enc,
                            const float* __restrict__ Kk, const float* __restrict__ Rk,
                            const float* __restrict__ Wq, const float* __restrict__ Wa)
{
    if (blockIdx.x == 0 && threadIdx.x == 0) { g_bar_count = 0u; g_bar_gen = 0u; }
    const int NWTK = N3U*UNITS, NWQ = UNITS*UNITS, NWA = UNITS*2*UNITS;
    const int total = NWTK + NWTK + NWQ + NWA + BT + NB*UNITS + NB*UNITS;
    for (int i = blockIdx.x*blockDim.x + threadIdx.x; i < total; i += gridDim.x*blockDim.x) {
        int j = i;
        if (j < NWTK) { int n = j >> 9, k = j & 511; g_WTK[j] = Kk[(EMB + k)*N3U + n]; continue; }
        j -= NWTK;
        if (j < NWTK) { int n = j >> 9, k = j & 511; g_WTR[j] = Rk[k*N3U + n]; continue; }
        j -= NWTK;
        if (j < NWQ)  { int u = j >> 9, k = j & 511; g_WqT[j] = Wq[k*UNITS + u]; continue; }
        j -= NWQ;
        if (j < NWA)  { int u = j >> 10, k = j & 1023; g_WaT[j] = Wa[k*UNITS + u]; continue; }
        j -= NWA;
        if (j < BT)   { int t = j >> 5, b = j & 31; g_rowtok[j] = x[b*NT + t]; continue; }
        j -= BT;
        if (j < NB*UNITS) {
            int b = j >> 9, u = j & 511;
            ((float*)g_hQ[0])[(((u >> 2) << 5) + b) * 4 + (u & 3)] = enc[j];
            continue;
        }
        j -= NB*UNITS;
        ((float*)g_attnQ[0])[j] = 0.0f;
    }
}

// ---------------- Wo split into pair-packed bf16 hi/lo -----------------------
__global__ void split_wo(const float* __restrict__ Wo)
{
    const int k2 = blockIdx.y;
    const int n = blockIdx.x * 256 + threadIdx.x;
    float f0 = Wo[(long)(2*k2)     * VOCAB + n];
    float f1 = Wo[(long)(2*k2 + 1) * VOCAB + n];
    uint32_t hi, lo;
    split_pack(f0, f1, hi, lo);
    g_WoHiP[(long)k2 * VOCAB + n] = hi;
    g_WoLoP[(long)k2 * VOCAB + n] = lo;
}

// ---------------- attn_all split into pair-packed bf16 hi/lo -----------------
__global__ void asplit()
{
    const int total = K2 * MROWS;
    for (int i = blockIdx.x*blockDim.x + threadIdx.x; i < total; i += gridDim.x*blockDim.x) {
        int row = i >> 8, k2 = i & 255;
        uint32_t hi = 0, lo = 0;
        if (row < BT) {
            float2 f = *(const float2*)(g_attn_all + (long)row * UNITS + (k2 << 1));
            split_pack(f.x, f.y, hi, lo);
        }
        g_AHiP[k2 * MROWS + row] = hi;
        g_ALoP[k2 * MROWS + row] = lo;
    }
}

// ---------------- MX transpose: [t*32+b][1536] -> [t][j][b] ------------------
__global__ void mxt_kernel()
{
    const int total = NT*N3U*NB;
    for (int i = blockIdx.x*blockDim.x + threadIdx.x; i < total; i += gridDim.x*blockDim.x) {
        int b = i & 31;
        int j = (i >> 5) % N3U;
        int t = i / (N3U * NB);
        g_MXT[i] = g_MX[((long)(t * 32 + b)) * N3U + j];
    }
}

// ---------------- generic 64x64 tiled SGEMM, optional gather/bias ------------
__global__ void sgemm64(const float* __restrict__ A, int lda,
                        const float* __restrict__ B, int ldb,
                        float* __restrict__ C, int ldc,
                        int M, int N, int K,
                        const float* __restrict__ bias,
                        const int* __restrict__ gather)
{
    __shared__ float As[16][64];
    __shared__ float Bs[16][64];
    const int t = threadIdx.x;
    const int row0 = blockIdx.y << 6;
    const int col0 = blockIdx.x << 6;
    const int a_row = t >> 2, a_k = (t & 3) << 2;
    const int b_k = t >> 4, b_c = (t & 15) << 2;
    const int ty = t >> 4, tx = t & 15;

    float acc[4][4];
    #pragma unroll
    for (int i = 0; i < 4; i++)
        #pragma unroll
        for (int j = 0; j < 4; j++) acc[i][j] = 0.0f;

    const float* Ar = nullptr;
    {
        int ar = row0 + a_row;
        if (ar < M) {
            long r = gather ? (long)gather[ar] : (long)ar;
            Ar = A + r * (long)lda;
        }
    }

    for (int k0 = 0; k0 < K; k0 += 16) {
        float4 av = make_float4(0.f, 0.f, 0.f, 0.f);
        if (Ar) av = *(const float4*)(Ar + k0 + a_k);
        As[a_k + 0][a_row] = av.x;
        As[a_k + 1][a_row] = av.y;
        As[a_k + 2][a_row] = av.z;
        As[a_k + 3][a_row] = av.w;
        *(float4*)&Bs[b_k][b_c] = *(const float4*)(B + (long)(k0 + b_k) * ldb + col0 + b_c);
        __syncthreads();
        #pragma unroll
        for (int k = 0; k < 16; k++) {
            float4 a4 = *(const float4*)&As[k][ty << 2];
            float4 b4 = *(const float4*)&Bs[k][tx << 2];
            float a[4] = {a4.x, a4.y, a4.z, a4.w};
            float b[4] = {b4.x, b4.y, b4.z, b4.w};
            #pragma unroll
            for (int i = 0; i < 4; i++)
                #pragma unroll
                for (int j = 0; j < 4; j++)
                    acc[i][j] = fmaf(a[i], b[j], acc[i][j]);
        }
        __syncthreads();
    }

    #pragma unroll
    for (int i = 0; i < 4; i++) {
        int r = row0 + (ty << 2) + i;
        if (r < M) {
            int c = col0 + (tx << 2);
            float4 o;
            o.x = acc[i][0] + (bias ? bias[c + 0] : 0.f);
            o.y = acc[i][1] + (bias ? bias[c + 1] : 0.f);
            o.z = acc[i][2] + (bias ? bias[c + 2] : 0.f);
            o.w = acc[i][3] + (bias ? bias[c + 3] : 0.f);
            *(float4*)(C + (long)r * ldc + c) = o;
        }
    }
}

// ---------------- bf16 split tensor-core logits GEMM -------------------------
__global__ __launch_bounds__(256) void bf16gemm(
    const uint32_t* __restrict__ Ahi, const uint32_t* __restrict__ Alo,
    const uint32_t* __restrict__ Bhi, const uint32_t* __restrict__ Blo,
    float* __restrict__ C, int M, const float* __restrict__ bias)
{
    __shared__ uint32_t AsHi[8][136], AsLo[8][136];   // [k2][row]
    __shared__ uint32_t BsHi[8][136], BsLo[8][136];   // [k2][n]
    const int t = threadIdx.x;
    const int w = t >> 5, lane = t & 31;
    const int wm = w >> 2, wn = w & 3;
    const int row0 = blockIdx.x << 7;
    const int col0 = blockIdx.y << 7;
    const int lr = lane >> 2, lc = lane & 3;

    float acc[4][4][4];
    #pragma unroll
    for (int mi = 0; mi < 4; mi++)
        #pragma unroll
        for (int ni = 0; ni < 4; ni++)
            #pragma unroll
            for (int q = 0; q < 4; q++) acc[mi][ni][q] = 0.0f;

    const int s_k2 = t >> 5, s_q = (t & 31) << 2;
    const uint32_t* ApH = Ahi + (long)s_k2 * MROWS + row0 + s_q;
    const uint32_t* ApL = Alo + (long)s_k2 * MROWS + row0 + s_q;
    const uint32_t* BpH = Bhi + (long)s_k2 * VOCAB + col0 + s_q;
    const uint32_t* BpL = Blo + (long)s_k2 * VOCAB + col0 + s_q;

    for (int c8 = 0; c8 < K2 / 8; c8++) {
        uint4 ah4 = *(const uint4*)(ApH + (long)(c8 * 8) * MROWS);
        uint4 al4 = *(const uint4*)(ApL + (long)(c8 * 8) * MROWS);
        uint4 bh4 = *(const uint4*)(BpH + (long)(c8 * 8) * VOCAB);
        uint4 bl4 = *(const uint4*)(BpL + (long)(c8 * 8) * VOCAB);
        __syncthreads();
        *(uint4*)&AsHi[s_k2][s_q] = ah4;
        *(uint4*)&AsLo[s_k2][s_q] = al4;
        *(uint4*)&BsHi[s_k2][s_q] = bh4;
        *(uint4*)&BsLo[s_k2][s_q] = bl4;
        __syncthreads();

        uint32_t ah[4][4], al[4][4];
        #pragma unroll
        for (int mi = 0; mi < 4; mi++) {
            const int r = (wm << 6) + (mi << 4) + lr;
            ah[mi][0] = AsHi[lc][r];     ah[mi][1] = AsHi[lc][r + 8];
            ah[mi][2] = AsHi[lc + 4][r]; ah[mi][3] = AsHi[lc + 4][r + 8];
            al[mi][0] = AsLo[lc][r];     al[mi][1] = AsLo[lc][r + 8];
            al[mi][2] = AsLo[lc + 4][r]; al[mi][3] = AsLo[lc + 4][r + 8];
        }
        #pragma unroll
        for (int ni = 0; ni < 4; ni++) {
            const int n = (wn << 5) + (ni << 3) + lr;
            uint32_t bh0 = BsHi[lc][n], bh1 = BsHi[lc + 4][n];
            uint32_t bl0 = BsLo[lc][n], bl1 = BsLo[lc + 4][n];
            #pragma unroll
            for (int mi = 0; mi < 4; mi++) {
                mma_bf16(acc[mi][ni], ah[mi], bh0, bh1);
                mma_bf16(acc[mi][ni], ah[mi], bl0, bl1);
                mma_bf16(acc[mi][ni], al[mi], bh0, bh1);
            }
        }
    }

    #pragma unroll
    for (int mi = 0; mi < 4; mi++) {
        const int r = row0 + (wm << 6) + (mi << 4) + lr;
        #pragma unroll
        for (int ni = 0; ni < 4; ni++) {
            const int c = col0 + (wn << 5) + (ni << 3) + (lc << 1);
            float2 bv = *(const float2*)(bias + c);
            if (r < M) {
                float2 o = {acc[mi][ni][0] + bv.x, acc[mi][ni][1] + bv.y};
                *(float2*)(C + (long)r * VOCAB + c) = o;
            }
            if (r + 8 < M) {
                float2 o = {acc[mi][ni][2] + bv.x, acc[mi][ni][3] + bv.y};
                *(float2*)(C + (long)(r + 8) * VOCAB + c) = o;
            }
        }
    }
}

// ------------- persistent recurrence: all 63 steps in one launch -------------
// RGRID=128 blocks x 1024 threads. GRU: block owns 4 u-cols, 32 warps =
// (4u x 2 family x 4 k-quarter), lane=batch. ATT: blocks 0..31, block=batch.
__global__ __launch_bounds__(1024, 1) void recur_all(
    const float* __restrict__ v_att, const float* __restrict__ memory,
    const float* __restrict__ gbias)
{
    __shared__ float red[4][2][4][3][32];   // [ul][f][kq][gate][lane]
    __shared__ float hs[UNITS], pqs[UNITS], vsh[UNITS], ctxs[UNITS];
    __shared__ float sc[NS];
    const int blk = blockIdx.x, tid = threadIdx.x;
    const int w = tid >> 5, lane = tid & 31;
    unsigned gen = 0;

    if (blk < NB && tid < UNITS) vsh[tid] = v_att[tid];

    for (int t = 0; t < NT; t++) {
        const int par = t & 1, npar = par ^ 1;

        // ---------- GRU phase ----------
        {
            const int ul = w >> 3, sub = w & 7;
            const int f = sub >> 2, kq = sub & 3;
            const int u = (blk << 2) + ul;
            const float4* __restrict__ act =
                (f ? g_hQ[par] : g_attnQ[par]) + (kq << 10);
            const float* __restrict__ wb = f ? g_WTR : g_WTK;
            const float* __restrict__ w0 = wb + ((long)u << 9) + (kq << 7);
            const float* __restrict__ w1 = w0 + (512 << 9);
            const float* __restrict__ w2 = w1 + (512 << 9);
            float az = 0.f, ar = 0.f, ah = 0.f;
            #pragma unroll 8
            for (int k4 = 0; k4 < 32; k4++) {
                float4 a  = act[(k4 << 5) + lane];
                float4 vz = *(const float4*)(w0 + (k4 << 2));
                float4 vr = *(const float4*)(w1 + (k4 << 2));
                float4 vh = *(const float4*)(w2 + (k4 << 2));
                az = fmaf(a.x, vz.x, az); ar = fmaf(a.x, vr.x, ar); ah = fmaf(a.x, vh.x, ah);
                az = fmaf(a.y, vz.y, az); ar = fmaf(a.y, vr.y, ar); ah = fmaf(a.y, vh.y, ah);
                az = fmaf(a.z, vz.z, az); ar = fmaf(a.z, vr.z, ar); ah = fmaf(a.z, vh.z, ah);
                az = fmaf(a.w, vz.w, az); ar = fmaf(a.w, vr.w, ar); ah = fmaf(a.w, vh.w, ah);
            }
            red[ul][f][kq][0][lane] = az;
            red[ul][f][kq][1][lane] = ar;
            red[ul][f][kq][2][lane] = ah;
        }
        __syncthreads();
        if (w < 4) {
            const int ul = w;
            const int u = (blk << 2) + ul;
            float xz = (red[ul][0][0][0][lane] + red[ul][0][1][0][lane])
                     + (red[ul][0][2][0][lane] + red[ul][0][3][0][lane]);
            float xr = (red[ul][0][0][1][lane] + red[ul][0][1][1][lane])
                     + (red[ul][0][2][1][lane] + red[ul][0][3][1][lane]);
            float xh = (red[ul][0][0][2][lane] + red[ul][0][1][2][lane])
                     + (red[ul][0][2][2][lane] + red[ul][0][3][2][lane]);
            float hz = (red[ul][1][0][0][lane] + red[ul][1][1][0][lane])
                     + (red[ul][1][2][0][lane] + red[ul][1][3][0][lane]);
            float hr = (red[ul][1][0][1][lane] + red[ul][1][1][1][lane])
                     + (red[ul][1][2][1][lane] + red[ul][1][3][1][lane]);
            float hhr = (red[ul][1][0][2][lane] + red[ul][1][1][2][lane])
                      + (red[ul][1][2][2][lane] + red[ul][1][3][2][lane]);

            const float* mx = g_MXT + (long)t * N3U * NB;
            float mz = mx[((u)        << 5) + lane];
            float mr = mx[((u + 512)  << 5) + lane];
            float mh = mx[((u + 1024) << 5) + lane];

            float z  = sigmoid_f(mz + xz + hz + gbias[N3U + u]);
            float r  = sigmoid_f(mr + xr + hr + gbias[N3U + 512 + u]);
            float hh = tanhf(mh + xh + r * (hhr + gbias[N3U + 1024 + u]));

            const int idx = ((((u >> 2) << 5) + lane) << 2) + (u & 3);
            float hold = ((const float*)g_hQ[par])[idx];
            ((float*)g_hQ[npar])[idx] = z * hold + (1.0f - z) * hh;
        }
        grid_barrier(gen);

        // ---------- ATT phase (blocks 0..31, b = blk) ----------
        if (blk < NB) {
            const int b = blk;
            if (tid < UNITS) {
                const float* hp = (const float*)g_hQ[npar];
                hs[tid] = hp[((((tid >> 2) << 5) + b) << 2) + (tid & 3)];
            }
            __syncthreads();

            // pq[u] = h . WqT[u]    (32 warps x 16 u each)
            #pragma unroll 1
            for (int uu = 0; uu < 16; uu++) {
                int u = (w << 4) + uu;
                const float* __restrict__ wr = g_WqT + ((long)u << 9);
                float acc = 0.f;
                #pragma unroll
                for (int j = 0; j < 4; j++) {
                    float4 wv = *(const float4*)(wr + (j << 7) + (lane << 2));
                    float4 hv = *(const float4*)(hs + (j << 7) + (lane << 2));
                    acc = fmaf(hv.x, wv.x, acc);
                    acc = fmaf(hv.y, wv.y, acc);
                    acc = fmaf(hv.z, wv.z, acc);
                    acc = fmaf(hv.w, wv.w, acc);
                }
                #pragma unroll
                for (int off = 16; off; off >>= 1) acc += __shfl_xor_sync(0xffffffffu, acc, off);
                if (lane == 0) pqs[u] = acc;
            }
            __syncthreads();

            // scores[s] = v . tanh(keys[s] + pq)    (32 warps x 4 s each)
            {
                const float* __restrict__ keysb = g_KEYS + (long)b * NS * UNITS;
                #pragma unroll 1
                for (int si = 0; si < 4; si++) {
                    int s = (w << 2) + si;
                    const float* kr = keysb + (s << 9);
                    float acc = 0.f;
                    #pragma unroll
                    for (int j = 0; j < 4; j++) {
                        float4 kv = *(const float4*)(kr + (j << 7) + (lane << 2));
                        float4 pv = *(const float4*)(pqs + (j << 7) + (lane << 2));
                        float4 vv = *(const float4*)(vsh + (j << 7) + (lane << 2));
                        acc = fmaf(vv.x, tanh_fast(kv.x + pv.x), acc);
                        acc = fmaf(vv.y, tanh_fast(kv.y + pv.y), acc);
                        acc = fmaf(vv.z, tanh_fast(kv.z + pv.z), acc);
                        acc = fmaf(vv.w, tanh_fast(kv.w + pv.w), acc);
                    }
                    #pragma unroll
                    for (int off = 16; off; off >>= 1) acc += __shfl_xor_sync(0xffffffffu, acc, off);
                    if (lane == 0) sc[s] = acc;
                }
            }
            __syncthreads();

            // softmax over 128 scores: single warp
            if (tid < 32) {
                float s0 = sc[tid], s1 = sc[tid + 32], s2 = sc[tid + 64], s3 = sc[tid + 96];
                float m = fmaxf(fmaxf(s0, s1), fmaxf(s2, s3));
                #pragma unroll
                for (int off = 16; off; off >>= 1) m = fmaxf(m, __shfl_xor_sync(0xffffffffu, m, off));
                float e0 = __expf(s0 - m), e1 = __expf(s1 - m);
                float e2 = __expf(s2 - m), e3 = __expf(s3 - m);
                float ss = (e0 + e1) + (e2 + e3);
                #pragma unroll
                for (int off = 16; off; off >>= 1) ss += __shfl_xor_sync(0xffffffffu, ss, off);
                float inv = 1.0f / ss;
                sc[tid] = e0 * inv; sc[tid + 32] = e1 * inv;
                sc[tid + 64] = e2 * inv; sc[tid + 96] = e3 * inv;
            }
            __syncthreads();

            // context[u] = sum_s align[s] * memory[b][s][u]
            {
                const float* __restrict__ memb = memory + (long)b * NS * UNITS;
                int u = tid & 511, sh = tid >> 9;
                float acc = 0.f;
                const float* mp = memb + ((sh << 6) << 9) + u;
                const float* scp = sc + (sh << 6);
                #pragma unroll 8
                for (int s = 0; s < 64; s++)
                    acc = fmaf(scp[s], mp[s << 9], acc);
                if (sh == 0) ctxs[u] = acc;
                __syncthreads();
                if (sh == 1) ctxs[u] += acc;
            }
            __syncthreads();

            // attn_new[u] = [h | ctx] . WaT[u]   (32 warps x 16 u each)
            {
                float* aq = (float*)g_attnQ[npar];
                #pragma unroll 1
                for (int uu = 0; uu < 16; uu++) {
                    int u = (w << 4) + uu;
                    const float* __restrict__ wr = g_WaT + ((long)u << 10);
                    float acc = 0.f;
                    #pragma unroll
                    for (int j = 0; j < 4; j++) {
                        float4 wv = *(const float4*)(wr + (j << 7) + (lane << 2));
                        float4 xv = *(const float4*)(hs + (j << 7) + (lane << 2));
                        acc = fmaf(xv.x, wv.x, acc);
                        acc = fmaf(xv.y, wv.y, acc);
                        acc = fmaf(xv.z, wv.z, acc);
                        acc = fmaf(xv.w, wv.w, acc);
                    }
                    #pragma unroll
                    for (int j = 0; j < 4; j++) {
                        float4 wv = *(const float4*)(wr + 512 + (j << 7) + (lane << 2));
                        float4 xv = *(const float4*)(ctxs + (j << 7) + (lane << 2));
                        acc = fmaf(xv.x, wv.x, acc);
                        acc = fmaf(xv.y, wv.y, acc);
                        acc = fmaf(xv.z, wv.z, acc);
                        acc = fmaf(xv.w, wv.w, acc);
                    }
                    #pragma unroll
                    for (int off = 16; off; off >>= 1) acc += __shfl_xor_sync(0xffffffffu, acc, off);
                    if (lane == 0) {
                        aq[((((u >> 2) << 5) + b) << 2) + (u & 3)] = acc;
                        g_attn_all[((long)(b * NT + t) << 9) + u] = acc;
                    }
                }
            }
        }
        grid_barrier(gen);
    }
}

extern "C" void kernel_launch(void* const* d_in, const int* in_sizes, int n_in,
                              void* d_out, int out_size) {
    const int*   x      = (const int*)d_in[0];
    const float* enc    = (const float*)d_in[1];
    const float* memory = (const float*)d_in[2];
    const float* E      = (const float*)d_in[3];
    const float* Kk     = (const float*)d_in[4];
    const float* Rk     = (const float*)d_in[5];
    const float* gbias  = (const float*)d_in[6];
    const float* Wq     = (const float*)d_in[7];
    const float* Wk     = (const float*)d_in[8];
    const float* v_att  = (const float*)d_in[9];
    const float* Wa     = (const float*)d_in[10];
    const float* Wo     = (const float*)d_in[11];
    const float* bo     = (const float*)d_in[12];
    float* out = (float*)d_out;

    void *pKEYS, *pMX, *pRT, *pWoHi, *pWoLo, *pAHi, *pALo;
    cudaGetSymbolAddress(&pKEYS, g_KEYS);
    cudaGetSymbolAddress(&pMX,   g_MX);
    cudaGetSymbolAddress(&pRT,   g_rowtok);
    cudaGetSymbolAddress(&pWoHi, g_WoHiP);
    cudaGetSymbolAddress(&pWoLo, g_WoLoP);
    cudaGetSymbolAddress(&pAHi,  g_AHiP);
    cudaGetSymbolAddress(&pALo,  g_ALoP);

    prep_kernel<<<256, 256>>>(x, enc, Kk, Rk, Wq, Wa);
    split_wo<<<dim3(125, 256), 256>>>(Wo);

    // keys = memory @ Wk : [4096,512] x [512,512]
    sgemm64<<<dim3(8, 64), 256>>>(memory, UNITS, Wk, UNITS,
                                  (float*)pKEYS, UNITS, NB*NS, UNITS, UNITS,
                                  nullptr, nullptr);
    // MX = E[rowtok] @ K_kernel[:256,:] + bias0 : [2016,256] x [256,1536]
    sgemm64<<<dim3(24, 32), 256>>>(E, EMB, Kk, N3U,
                                   (float*)pMX, N3U, BT, N3U, EMB,
                                   gbias, (const int*)pRT);
    mxt_kernel<<<512, 256>>>();

    // entire 63-step recurrence in one persistent launch
    recur_all<<<RGRID, 1024>>>(v_att, memory, gbias);

    // pack attn_all into bf16 hi/lo, then logits = attn_all @ Wo + bo
    asplit<<<512, 256>>>();
    bf16gemm<<<dim3(16, VOCAB / 128), 256>>>((const uint32_t*)pAHi,
                                             (const uint32_t*)pALo,
                                             (const uint32_t*)pWoHi,
                                             (const uint32_t*)pWoLo,
                                             out, BT, bo);
}

// round 16
// speedup vs baseline: 3.0948x; 1.1544x over previous
#include <cuda_runtime.h>
#include <cuda_bf16.h>
#include <math.h>
#include <stdint.h>

#define VOCAB 32000
#define EMB   256
#define UNITS 512
#define NB    32
#define NS    128
#define NT    63
#define N3U   1536
#define BT    (NB*NT)
#define K2    256          // UNITS/2 packed bf16 pairs
#define MROWS 2048         // BT padded to 128
#define RGRID 128          // persistent recurrence grid (< 148 SMs)

__device__ float  g_MX [NT*NB*N3U];
__device__ float  g_MXT[NT*N3U*NB];
__device__ float  g_KEYS[NB*NS*UNITS];
__device__ float  g_WTK[N3U*UNITS];
__device__ float  g_WTR[N3U*UNITS];
__device__ float  g_WqT[UNITS*UNITS];
__device__ float  g_WaT[UNITS*2*UNITS];
__device__ float4 g_hQ  [2][128*32];     // [k4][b] packed
__device__ float4 g_attnQ[2][128*32];
__device__ float4 g_ctxQ[128*32];        // context, k-grouped
__device__ float  g_pq[NB*UNITS];        // pq plain [b][u]
__device__ float  g_attn_all[BT*UNITS];
__device__ int    g_rowtok[BT];
__device__ uint32_t g_WoHiP[K2*VOCAB];
__device__ uint32_t g_WoLoP[K2*VOCAB];
__device__ uint32_t g_AHiP[K2*MROWS];
__device__ uint32_t g_ALoP[K2*MROWS];
__device__ unsigned g_bar_count;
__device__ unsigned g_bar_gen;

__device__ __forceinline__ float sigmoid_f(float x) {
    return 1.0f / (1.0f + __expf(-x));
}
__device__ __forceinline__ float tanh_fast(float x) {
    float y; asm("tanh.approx.f32 %0, %1;" : "=f"(y) : "f"(x)); return y;
}
__device__ __forceinline__ void split_pack(float f0, float f1,
                                           uint32_t& hi, uint32_t& lo) {
    __nv_bfloat16 h0 = __float2bfloat16_rn(f0);
    __nv_bfloat16 h1 = __float2bfloat16_rn(f1);
    __nv_bfloat16 l0 = __float2bfloat16_rn(f0 - __bfloat162float(h0));
    __nv_bfloat16 l1 = __float2bfloat16_rn(f1 - __bfloat162float(h1));
    hi = (uint32_t)*(uint16_t*)&h0 | ((uint32_t)*(uint16_t*)&h1 << 16);
    lo = (uint32_t)*(uint16_t*)&l0 | ((uint32_t)*(uint16_t*)&l1 << 16);
}
__device__ __forceinline__ void mma_bf16(float* d, const uint32_t* a,
                                         uint32_t b0, uint32_t b1) {
    asm volatile("mma.sync.aligned.m16n8k16.row.col.f32.bf16.bf16.f32 "
        "{%0,%1,%2,%3}, {%4,%5,%6,%7}, {%8,%9}, {%0,%1,%2,%3};"
        : "+f"(d[0]), "+f"(d[1]), "+f"(d[2]), "+f"(d[3])
        : "r"(a[0]), "r"(a[1]), "r"(a[2]), "r"(a[3]), "r"(b0), "r"(b1));
}

// Grid barrier: arrival via atomicAdd; release+poll via volatile (no L2-atomic
// serialization on the poll path). RGRID=128 <= 148 SMs -> wave-1 co-residency.
__device__ __forceinline__ void grid_barrier(unsigned& gen)
{
    __syncthreads();
    if (threadIdx.x == 0) {
        __threadfence();
        if (atomicAdd(&g_bar_count, 1u) == RGRID - 1) {
            g_bar_count = 0u;
            __threadfence();
            *(volatile unsigned*)&g_bar_gen = gen + 1u;
        } else {
            while (*(volatile unsigned*)&g_bar_gen <= gen) { }
        }
        __threadfence();
    }
    __syncthreads();
    gen++;
}

// ------------------------- prep: transposes + init ---------------------------
__global__ void prep_kernel(const int* __restrict__ x, const float* __restrict__ enc,
                            const float* __restrict__ Kk, const float* __restrict__ Rk,
                            const float* __restrict__ Wq, const float* __restrict__ Wa)
{
    if (blockIdx.x == 0 && threadIdx.x == 0) { g_bar_count = 0u; g_bar_gen = 0u; }
    const int NWTK = N3U*UNITS, NWQ = UNITS*UNITS, NWA = UNITS*2*UNITS;
    const int total = NWTK + NWTK + NWQ + NWA + BT + NB*UNITS + NB*UNITS;
    for (int i = blockIdx.x*blockDim.x + threadIdx.x; i < total; i += gridDim.x*blockDim.x) {
        int j = i;
        if (j < NWTK) { int n = j >> 9, k = j & 511; g_WTK[j] = Kk[(EMB + k)*N3U + n]; continue; }
        j -= NWTK;
        if (j < NWTK) { int n = j >> 9, k = j & 511; g_WTR[j] = Rk[k*N3U + n]; continue; }
        j -= NWTK;
        if (j < NWQ)  { int u = j >> 9, k = j & 511; g_WqT[j] = Wq[k*UNITS + u]; continue; }
        j -= NWQ;
        if (j < NWA)  { int u = j >> 10, k = j & 1023; g_WaT[j] = Wa[k*UNITS + u]; continue; }
        j -= NWA;
        if (j < BT)   { int t = j >> 5, b = j & 31; g_rowtok[j] = x[b*NT + t]; continue; }
        j -= BT;
        if (j < NB*UNITS) {
            int b = j >> 9, u = j & 511;
            ((float*)g_hQ[0])[(((u >> 2) << 5) + b) * 4 + (u & 3)] = enc[j];
            continue;
        }
        j -= NB*UNITS;
        ((float*)g_attnQ[0])[j] = 0.0f;
    }
}

// ---------------- Wo split into pair-packed bf16 hi/lo -----------------------
__global__ void split_wo(const float* __restrict__ Wo)
{
    const int k2 = blockIdx.y;
    const int n = blockIdx.x * 256 + threadIdx.x;
    float f0 = Wo[(long)(2*k2)     * VOCAB + n];
    float f1 = Wo[(long)(2*k2 + 1) * VOCAB + n];
    uint32_t hi, lo;
    split_pack(f0, f1, hi, lo);
    g_WoHiP[(long)k2 * VOCAB + n] = hi;
    g_WoLoP[(long)k2 * VOCAB + n] = lo;
}

// ---------------- attn_all split into pair-packed bf16 hi/lo -----------------
__global__ void asplit()
{
    const int total = K2 * MROWS;
    for (int i = blockIdx.x*blockDim.x + threadIdx.x; i < total; i += gridDim.x*blockDim.x) {
        int row = i >> 8, k2 = i & 255;
        uint32_t hi = 0, lo = 0;
        if (row < BT) {
            float2 f = *(const float2*)(g_attn_all + (long)row * UNITS + (k2 << 1));
            split_pack(f.x, f.y, hi, lo);
        }
        g_AHiP[k2 * MROWS + row] = hi;
        g_ALoP[k2 * MROWS + row] = lo;
    }
}

// ---------------- MX transpose: [t*32+b][1536] -> [t][j][b] ------------------
__global__ void mxt_kernel()
{
    const int total = NT*N3U*NB;
    for (int i = blockIdx.x*blockDim.x + threadIdx.x; i < total; i += gridDim.x*blockDim.x) {
        int b = i & 31;
        int j = (i >> 5) % N3U;
        int t = i / (N3U * NB);
        g_MXT[i] = g_MX[((long)(t * 32 + b)) * N3U + j];
    }
}

// ---------------- generic 64x64 tiled SGEMM, optional gather/bias ------------
__global__ void sgemm64(const float* __restrict__ A, int lda,
                        const float* __restrict__ B, int ldb,
                        float* __restrict__ C, int ldc,
                        int M, int N, int K,
                        const float* __restrict__ bias,
                        const int* __restrict__ gather)
{
    __shared__ float As[16][64];
    __shared__ float Bs[16][64];
    const int t = threadIdx.x;
    const int row0 = blockIdx.y << 6;
    const int col0 = blockIdx.x << 6;
    const int a_row = t >> 2, a_k = (t & 3) << 2;
    const int b_k = t >> 4, b_c = (t & 15) << 2;
    const int ty = t >> 4, tx = t & 15;

    float acc[4][4];
    #pragma unroll
    for (int i = 0; i < 4; i++)
        #pragma unroll
        for (int j = 0; j < 4; j++) acc[i][j] = 0.0f;

    const float* Ar = nullptr;
    {
        int ar = row0 + a_row;
        if (ar < M) {
            long r = gather ? (long)gather[ar] : (long)ar;
            Ar = A + r * (long)lda;
        }
    }

    for (int k0 = 0; k0 < K; k0 += 16) {
        float4 av = make_float4(0.f, 0.f, 0.f, 0.f);
        if (Ar) av = *(const float4*)(Ar + k0 + a_k);
        As[a_k + 0][a_row] = av.x;
        As[a_k + 1][a_row] = av.y;
        As[a_k + 2][a_row] = av.z;
        As[a_k + 3][a_row] = av.w;
        *(float4*)&Bs[b_k][b_c] = *(const float4*)(B + (long)(k0 + b_k) * ldb + col0 + b_c);
        __syncthreads();
        #pragma unroll
        for (int k = 0; k < 16; k++) {
            float4 a4 = *(const float4*)&As[k][ty << 2];
            float4 b4 = *(const float4*)&Bs[k][tx << 2];
            float a[4] = {a4.x, a4.y, a4.z, a4.w};
            float b[4] = {b4.x, b4.y, b4.z, b4.w};
            #pragma unroll
            for (int i = 0; i < 4; i++)
                #pragma unroll
                for (int j = 0; j < 4; j++)
                    acc[i][j] = fmaf(a[i], b[j], acc[i][j]);
        }
        __syncthreads();
    }

    #pragma unroll
    for (int i = 0; i < 4; i++) {
        int r = row0 + (ty << 2) + i;
        if (r < M) {
            int c = col0 + (tx << 2);
            float4 o;
            o.x = acc[i][0] + (bias ? bias[c + 0] : 0.f);
            o.y = acc[i][1] + (bias ? bias[c + 1] : 0.f);
            o.z = acc[i][2] + (bias ? bias[c + 2] : 0.f);
            o.w = acc[i][3] + (bias ? bias[c + 3] : 0.f);
            *(float4*)(C + (long)r * ldc + c) = o;
        }
    }
}

// ---------------- bf16 split tensor-core logits GEMM -------------------------
// 512 threads, 16 warps (4x4), warp tile 32x32, double-buffered smem with
// register prefetch. 3-term split: hi*hi + hi*lo + lo*hi.
__global__ __launch_bounds__(512) void bf16gemm(
    const uint32_t* __restrict__ Ahi, const uint32_t* __restrict__ Alo,
    const uint32_t* __restrict__ Bhi, const uint32_t* __restrict__ Blo,
    float* __restrict__ C, int M, const float* __restrict__ bias)
{
    __shared__ uint32_t AsHi[2][8][136], AsLo[2][8][136];
    __shared__ uint32_t BsHi[2][8][136], BsLo[2][8][136];
    const int t = threadIdx.x;
    const int w = t >> 5, lane = t & 31;
    const int wm = w >> 2, wn = w & 3;
    const int row0 = blockIdx.x << 7;
    const int col0 = blockIdx.y << 7;
    const int lr = lane >> 2, lc = lane & 3;

    float acc[2][4][4];
    #pragma unroll
    for (int mi = 0; mi < 2; mi++)
        #pragma unroll
        for (int ni = 0; ni < 4; ni++)
            #pragma unroll
            for (int q = 0; q < 4; q++) acc[mi][ni][q] = 0.0f;

    const int s_k2 = t >> 6;             // 0..7
    const int s_q  = (t & 63) << 1;      // 0..126
    const uint32_t* ApH = Ahi + (long)s_k2 * MROWS + row0 + s_q;
    const uint32_t* ApL = Alo + (long)s_k2 * MROWS + row0 + s_q;
    const uint32_t* BpH = Bhi + (long)s_k2 * VOCAB + col0 + s_q;
    const uint32_t* BpL = Blo + (long)s_k2 * VOCAB + col0 + s_q;

    uint2 ah2 = *(const uint2*)ApH;
    uint2 al2 = *(const uint2*)ApL;
    uint2 bh2 = *(const uint2*)BpH;
    uint2 bl2 = *(const uint2*)BpL;
    *(uint2*)&AsHi[0][s_k2][s_q] = ah2;
    *(uint2*)&AsLo[0][s_k2][s_q] = al2;
    *(uint2*)&BsHi[0][s_k2][s_q] = bh2;
    *(uint2*)&BsLo[0][s_k2][s_q] = bl2;
    __syncthreads();

    for (int c8 = 0; c8 < K2 / 8; c8++) {
        const int cur = c8 & 1;
        if (c8 < K2 / 8 - 1) {
            long off = (long)((c8 + 1) << 3);
            ah2 = *(const uint2*)(ApH + off * MROWS);
            al2 = *(const uint2*)(ApL + off * MROWS);
            bh2 = *(const uint2*)(BpH + off * VOCAB);
            bl2 = *(const uint2*)(BpL + off * VOCAB);
        }

        uint32_t a_hi[2][4], a_lo[2][4];
        #pragma unroll
        for (int mi = 0; mi < 2; mi++) {
            const int r = (wm << 5) + (mi << 4) + lr;
            a_hi[mi][0] = AsHi[cur][lc][r];     a_hi[mi][1] = AsHi[cur][lc][r + 8];
            a_hi[mi][2] = AsHi[cur][lc + 4][r]; a_hi[mi][3] = AsHi[cur][lc + 4][r + 8];
            a_lo[mi][0] = AsLo[cur][lc][r];     a_lo[mi][1] = AsLo[cur][lc][r + 8];
            a_lo[mi][2] = AsLo[cur][lc + 4][r]; a_lo[mi][3] = AsLo[cur][lc + 4][r + 8];
        }
        #pragma unroll
        for (int ni = 0; ni < 4; ni++) {
            const int n = (wn << 5) + (ni << 3) + lr;
            uint32_t bh0 = BsHi[cur][lc][n], bh1 = BsHi[cur][lc + 4][n];
            uint32_t bl0 = BsLo[cur][lc][n], bl1 = BsLo[cur][lc + 4][n];
            #pragma unroll
            for (int mi = 0; mi < 2; mi++) {
                mma_bf16(acc[mi][ni], a_hi[mi], bh0, bh1);
                mma_bf16(acc[mi][ni], a_hi[mi], bl0, bl1);
                mma_bf16(acc[mi][ni], a_lo[mi], bh0, bh1);
            }
        }
        if (c8 < K2 / 8 - 1) {
            const int nxt = cur ^ 1;
            *(uint2*)&AsHi[nxt][s_k2][s_q] = ah2;
            *(uint2*)&AsLo[nxt][s_k2][s_q] = al2;
            *(uint2*)&BsHi[nxt][s_k2][s_q] = bh2;
            *(uint2*)&BsLo[nxt][s_k2][s_q] = bl2;
        }
        __syncthreads();
    }

    #pragma unroll
    for (int mi = 0; mi < 2; mi++) {
        const int r = row0 + (wm << 5) + (mi << 4) + lr;
        #pragma unroll
        for (int ni = 0; ni < 4; ni++) {
            const int c = col0 + (wn << 5) + (ni << 3) + (lc << 1);
            float2 bv = *(const float2*)(bias + c);
            if (r < M) {
                float2 o = {acc[mi][ni][0] + bv.x, acc[mi][ni][1] + bv.y};
                *(float2*)(C + (long)r * VOCAB + c) = o;
            }
            if (r + 8 < M) {
                float2 o = {acc[mi][ni][2] + bv.x, acc[mi][ni][3] + bv.y};
                *(float2*)(C + (long)(r + 8) * VOCAB + c) = o;
            }
        }
    }
}

// ------------- persistent recurrence: all 63 steps in one launch -------------
// Phases per step (4 grid barriers):
//   GRU (128 blk, u-split 4u) -> PQ (128 blk, u-split) ->
//   SCORES+SOFTMAX+CTX (32 blk, b=blk) -> WA (128 blk, u-split)
__global__ __launch_bounds__(1024, 1) void recur_all(
    const float* __restrict__ v_att, const float* __restrict__ memory,
    const float* __restrict__ gbias)
{
    __shared__ float red[4][2][4][3][32];   // GRU partials
    __shared__ float red2[4][8][32];        // PQ/WA partials
    __shared__ float pqs[UNITS], vsh[UNITS], ctxs[UNITS];
    __shared__ float sc[NS];
    const int blk = blockIdx.x, tid = threadIdx.x;
    const int w = tid >> 5, lane = tid & 31;
    unsigned gen = 0;

    if (blk < NB && tid < UNITS) vsh[tid] = v_att[tid];

    for (int t = 0; t < NT; t++) {
        const int par = t & 1, npar = par ^ 1;

        // ---------- GRU ----------
        {
            const int ul = w >> 3, sub = w & 7;
            const int f = sub >> 2, kq = sub & 3;
            const int u = (blk << 2) + ul;
            const float4* __restrict__ act =
                (f ? g_hQ[par] : g_attnQ[par]) + (kq << 10);
            const float* __restrict__ wb = f ? g_WTR : g_WTK;
            const float* __restrict__ w0 = wb + ((long)u << 9) + (kq << 7);
            const float* __restrict__ w1 = w0 + (512 << 9);
            const float* __restrict__ w2 = w1 + (512 << 9);
            float az = 0.f, ar = 0.f, ah = 0.f;
            #pragma unroll 8
            for (int k4 = 0; k4 < 32; k4++) {
                float4 a  = act[(k4 << 5) + lane];
                float4 vz = *(const float4*)(w0 + (k4 << 2));
                float4 vr = *(const float4*)(w1 + (k4 << 2));
                float4 vh = *(const float4*)(w2 + (k4 << 2));
                az = fmaf(a.x, vz.x, az); ar = fmaf(a.x, vr.x, ar); ah = fmaf(a.x, vh.x, ah);
                az = fmaf(a.y, vz.y, az); ar = fmaf(a.y, vr.y, ar); ah = fmaf(a.y, vh.y, ah);
                az = fmaf(a.z, vz.z, az); ar = fmaf(a.z, vr.z, ar); ah = fmaf(a.z, vh.z, ah);
                az = fmaf(a.w, vz.w, az); ar = fmaf(a.w, vr.w, ar); ah = fmaf(a.w, vh.w, ah);
            }
            red[ul][f][kq][0][lane] = az;
            red[ul][f][kq][1][lane] = ar;
            red[ul][f][kq][2][lane] = ah;
        }
        __syncthreads();
        if (w < 4) {
            const int ul = w;
            const int u = (blk << 2) + ul;
            float xz = (red[ul][0][0][0][lane] + red[ul][0][1][0][lane])
                     + (red[ul][0][2][0][lane] + red[ul][0][3][0][lane]);
            float xr = (red[ul][0][0][1][lane] + red[ul][0][1][1][lane])
                     + (red[ul][0][2][1][lane] + red[ul][0][3][1][lane]);
            float xh = (red[ul][0][0][2][lane] + red[ul][0][1][2][lane])
                     + (red[ul][0][2][2][lane] + red[ul][0][3][2][lane]);
            float hz = (red[ul][1][0][0][lane] + red[ul][1][1][0][lane])
                     + (red[ul][1][2][0][lane] + red[ul][1][3][0][lane]);
            float hr = (red[ul][1][0][1][lane] + red[ul][1][1][1][lane])
                     + (red[ul][1][2][1][lane] + red[ul][1][3][1][lane]);
            float hhr = (red[ul][1][0][2][lane] + red[ul][1][1][2][lane])
                      + (red[ul][1][2][2][lane] + red[ul][1][3][2][lane]);

            const float* mx = g_MXT + (long)t * N3U * NB;
            float mz = mx[((u)        << 5) + lane];
            float mr = mx[((u + 512)  << 5) + lane];
            float mh = mx[((u + 1024) << 5) + lane];

            float z  = sigmoid_f(mz + xz + hz + gbias[N3U + u]);
            float r  = sigmoid_f(mr + xr + hr + gbias[N3U + 512 + u]);
            float hh = tanhf(mh + xh + r * (hhr + gbias[N3U + 1024 + u]));

            const int idx = ((((u >> 2) << 5) + lane) << 2) + (u & 3);
            float hold = ((const float*)g_hQ[par])[idx];
            ((float*)g_hQ[npar])[idx] = z * hold + (1.0f - z) * hh;
        }
        grid_barrier(gen);

        // ---------- PQ (u-split): pq[b][u] = h . WqT[u] ----------
        {
            const int ul = w >> 3, kq = w & 7;     // kq covers 64 k = 16 k4
            const int u = (blk << 2) + ul;
            const float4* __restrict__ act = g_hQ[npar] + (kq << 9);
            const float* __restrict__ wr = g_WqT + ((long)u << 9) + (kq << 6);
            float a = 0.f;
            #pragma unroll
            for (int i = 0; i < 16; i++) {
                float4 av = act[(i << 5) + lane];
                float4 wv = *(const float4*)(wr + (i << 2));
                a = fmaf(av.x, wv.x, a); a = fmaf(av.y, wv.y, a);
                a = fmaf(av.z, wv.z, a); a = fmaf(av.w, wv.w, a);
            }
            red2[ul][kq][lane] = a;
        }
        __syncthreads();
        if (w < 4) {
            const int u = (blk << 2) + w;
            float s = ((red2[w][0][lane] + red2[w][1][lane])
                     + (red2[w][2][lane] + red2[w][3][lane]))
                    + ((red2[w][4][lane] + red2[w][5][lane])
                     + (red2[w][6][lane] + red2[w][7][lane]));
            g_pq[lane * UNITS + u] = s;
        }
        grid_barrier(gen);

        // ---------- SCORES + SOFTMAX + CTX (blocks 0..31, b = blk) ----------
        if (blk < NB) {
            const int b = blk;
            if (tid < UNITS) pqs[tid] = g_pq[b * UNITS + tid];
            __syncthreads();

            const float* __restrict__ keysb = g_KEYS + (long)b * NS * UNITS;
            #pragma unroll 1
            for (int si = 0; si < 4; si++) {
                int s = (w << 2) + si;
                const float* kr = keysb + (s << 9);
                float acc = 0.f;
                #pragma unroll
                for (int j = 0; j < 4; j++) {
                    float4 kv = *(const float4*)(kr + (j << 7) + (lane << 2));
                    float4 pv = *(const float4*)(pqs + (j << 7) + (lane << 2));
                    float4 vv = *(const float4*)(vsh + (j << 7) + (lane << 2));
                    acc = fmaf(vv.x, tanh_fast(kv.x + pv.x), acc);
                    acc = fmaf(vv.y, tanh_fast(kv.y + pv.y), acc);
                    acc = fmaf(vv.z, tanh_fast(kv.z + pv.z), acc);
                    acc = fmaf(vv.w, tanh_fast(kv.w + pv.w), acc);
                }
                #pragma unroll
                for (int off = 16; off; off >>= 1) acc += __shfl_xor_sync(0xffffffffu, acc, off);
                if (lane == 0) sc[s] = acc;
            }
            __syncthreads();

            if (tid < 32) {
                float s0 = sc[tid], s1 = sc[tid + 32], s2 = sc[tid + 64], s3 = sc[tid + 96];
                float m = fmaxf(fmaxf(s0, s1), fmaxf(s2, s3));
                #pragma unroll
                for (int off = 16; off; off >>= 1) m = fmaxf(m, __shfl_xor_sync(0xffffffffu, m, off));
                float e0 = __expf(s0 - m), e1 = __expf(s1 - m);
                float e2 = __expf(s2 - m), e3 = __expf(s3 - m);
                float ss = (e0 + e1) + (e2 + e3);
                #pragma unroll
                for (int off = 16; off; off >>= 1) ss += __shfl_xor_sync(0xffffffffu, ss, off);
                float inv = 1.0f / ss;
                sc[tid] = e0 * inv; sc[tid + 32] = e1 * inv;
                sc[tid + 64] = e2 * inv; sc[tid + 96] = e3 * inv;
            }
            __syncthreads();

            {
                const float* __restrict__ memb = memory + (long)b * NS * UNITS;
                int u = tid & 511, sh = tid >> 9;
                float acc = 0.f;
                const float* mp = memb + ((sh << 6) << 9) + u;
                const float* scp = sc + (sh << 6);
                #pragma unroll 8
                for (int s = 0; s < 64; s++)
                    acc = fmaf(scp[s], mp[s << 9], acc);
                if (sh == 0) ctxs[u] = acc;
                __syncthreads();
                if (sh == 1) ctxs[u] += acc;
            }
            __syncthreads();
            if (tid < UNITS) {
                ((float*)g_ctxQ)[((((tid >> 2) << 5) + b) << 2) + (tid & 3)] = ctxs[tid];
            }
        }
        grid_barrier(gen);

        // ---------- WA (u-split): attn[b][u] = [h|ctx] . WaT[u] ----------
        {
            const int ul = w >> 3, kq = w & 7;     // kq covers 128 k = 32 k4
            const int u = (blk << 2) + ul;
            const float4* __restrict__ act =
                (kq < 4) ? (g_hQ[npar] + (kq << 10)) : (g_ctxQ + ((kq - 4) << 10));
            const float* __restrict__ wr = g_WaT + ((long)u << 10) + (kq << 7);
            float a = 0.f;
            #pragma unroll 8
            for (int i = 0; i < 32; i++) {
                float4 av = act[(i << 5) + lane];
                float4 wv = *(const float4*)(wr + (i << 2));
                a = fmaf(av.x, wv.x, a); a = fmaf(av.y, wv.y, a);
                a = fmaf(av.z, wv.z, a); a = fmaf(av.w, wv.w, a);
            }
            red2[ul][kq][lane] = a;
        }
        __syncthreads();
        if (w < 4) {
            const int u = (blk << 2) + w;
            float s = ((red2[w][0][lane] + red2[w][1][lane])
                     + (red2[w][2][lane] + red2[w][3][lane]))
                    + ((red2[w][4][lane] + red2[w][5][lane])
                     + (red2[w][6][lane] + red2[w][7][lane]));
            ((float*)g_attnQ[npar])[((((u >> 2) << 5) + lane) << 2) + (u & 3)] = s;
            g_attn_all[((long)(lane * NT + t) << 9) + u] = s;
        }
        grid_barrier(gen);
    }
}

extern "C" void kernel_launch(void* const* d_in, const int* in_sizes, int n_in,
                              void* d_out, int out_size) {
    const int*   x      = (const int*)d_in[0];
    const float* enc    = (const float*)d_in[1];
    const float* memory = (const float*)d_in[2];
    const float* E      = (const float*)d_in[3];
    const float* Kk     = (const float*)d_in[4];
    const float* Rk     = (const float*)d_in[5];
    const float* gbias  = (const float*)d_in[6];
    const float* Wq     = (const float*)d_in[7];
    const float* Wk     = (const float*)d_in[8];
    const float* v_att  = (const float*)d_in[9];
    const float* Wa     = (const float*)d_in[10];
    const float* Wo     = (const float*)d_in[11];
    const float* bo     = (const float*)d_in[12];
    float* out = (float*)d_out;

    void *pKEYS, *pMX, *pRT, *pWoHi, *pWoLo, *pAHi, *pALo;
    cudaGetSymbolAddress(&pKEYS, g_KEYS);
    cudaGetSymbolAddress(&pMX,   g_MX);
    cudaGetSymbolAddress(&pRT,   g_rowtok);
    cudaGetSymbolAddress(&pWoHi, g_WoHiP);
    cudaGetSymbolAddress(&pWoLo, g_WoLoP);
    cudaGetSymbolAddress(&pAHi,  g_AHiP);
    cudaGetSymbolAddress(&pALo,  g_ALoP);

    prep_kernel<<<256, 256>>>(x, enc, Kk, Rk, Wq, Wa);
    split_wo<<<dim3(125, 256), 256>>>(Wo);

    // keys = memory @ Wk : [4096,512] x [512,512]
    sgemm64<<<dim3(8, 64), 256>>>(memory, UNITS, Wk, UNITS,
                                  (float*)pKEYS, UNITS, NB*NS, UNITS, UNITS,
                                  nullptr, nullptr);
    // MX = E[rowtok] @ K_kernel[:256,:] + bias0 : [2016,256] x [256,1536]
    sgemm64<<<dim3(24, 32), 256>>>(E, EMB, Kk, N3U,
                                   (float*)pMX, N3U, BT, N3U, EMB,
                                   gbias, (const int*)pRT);
    mxt_kernel<<<512, 256>>>();

    // entire 63-step recurrence in one persistent launch
    recur_all<<<RGRID, 1024>>>(v_att, memory, gbias);

    // pack attn_all into bf16 hi/lo, then logits = attn_all @ Wo + bo
    asplit<<<512, 256>>>();
    bf16gemm<<<dim3(16, VOCAB / 128), 512>>>((const uint32_t*)pAHi,
                                             (const uint32_t*)pALo,
                                             (const uint32_t*)pWoHi,
                                             (const uint32_t*)pWoLo,
                                             out, BT, bo);
}